// round 13
// baseline (speedup 1.0000x reference)
#include <cuda_runtime.h>
#include <cuda_bf16.h>
#include <cstdint>

// Problem constants
#define BB 2
#define TT 4096
#define CC 128
#define HH 8
#define DD 16
#define MROWS (BB*TT)          // 8192
#define NBH (BB*HH)            // 16

// Scratch (device globals; no allocation allowed)
__device__ __nv_bfloat16 g_wb[4*128*256];    // [sel][j][hi128|lo128] (Wk,Wq,Wv,Wp)
__device__ __nv_bfloat16 g_qb[NBH*TT*DD];    // [bh][t][16] bf16 (pre-scaled 0.25)
__device__ __nv_bfloat16 g_kb[NBH*TT*DD];    // [bh][t][16] bf16
__device__ __nv_bfloat16 g_vth[NBH*DD*TT];   // V hi, transposed: [bh*16+d][t]
__device__ __nv_bfloat16 g_vtl[NBH*DD*TT];   // V lo, transposed: [bh*16+d][t]
__device__ float g_att[MROWS*CC];            // unnormalized attn accum (atomic)
__device__ float g_l[MROWS*HH];              // row sums (atomic)

// ============================================================================
// Helpers
// ============================================================================
__device__ __forceinline__ void mma16816(float d[4], const uint32_t a[4], const uint32_t b[2]) {
    asm volatile("mma.sync.aligned.m16n8k16.row.col.f32.bf16.bf16.f32 "
        "{%0,%1,%2,%3}, {%4,%5,%6,%7}, {%8,%9}, {%0,%1,%2,%3};"
        : "+f"(d[0]), "+f"(d[1]), "+f"(d[2]), "+f"(d[3])
        : "r"(a[0]), "r"(a[1]), "r"(a[2]), "r"(a[3]), "r"(b[0]), "r"(b[1]));
}
__device__ __forceinline__ void mma16816_init(float d[4], const uint32_t a[4], const uint32_t b[2]) {
    asm volatile("mma.sync.aligned.m16n8k16.row.col.f32.bf16.bf16.f32 "
        "{%0,%1,%2,%3}, {%4,%5,%6,%7}, {%8,%9}, {%10,%10,%10,%10};"
        : "=f"(d[0]), "=f"(d[1]), "=f"(d[2]), "=f"(d[3])
        : "r"(a[0]), "r"(a[1]), "r"(a[2]), "r"(a[3]), "r"(b[0]), "r"(b[1]), "f"(0.0f));
}
__device__ __forceinline__ uint32_t pack2(float lo_el, float hi_el) {
    __nv_bfloat162 h = __floats2bfloat162_rn(lo_el, hi_el);
    return *reinterpret_cast<uint32_t*>(&h);
}
__device__ __forceinline__ float bflo(uint32_t u) { uint32_t v = u << 16;         return __uint_as_float(v); }
__device__ __forceinline__ float bfhi(uint32_t u) { uint32_t v = u & 0xFFFF0000u; return __uint_as_float(v); }
__device__ __forceinline__ float exp_poly(float y) {  // |y| <~ 0.5
    float t = fmaf(y, 0.041666668f, 0.16666667f);
    t = fmaf(y, t, 0.5f);
    t = fmaf(y, t, 1.0f);
    t = fmaf(y, t, 1.0f);
    return t;
}
__device__ __forceinline__ float fast_rcp(float x) {
    float r; asm("rcp.approx.f32 %0, %1;" : "=f"(r) : "f"(x));
    return r * (2.0f - x * r);   // one Newton step
}
#define CP_ASYNC16(dst_u32, src_ptr) \
    asm volatile("cp.async.ca.shared.global [%0], [%1], 16;" :: "r"(dst_u32), "l"(src_ptr))
#define CP_COMMIT() asm volatile("cp.async.commit_group;" ::: "memory")
#define CP_WAIT0()  asm volatile("cp.async.wait_group 0;" ::: "memory")
#define CP_WAIT1()  asm volatile("cp.async.wait_group 1;" ::: "memory")
#define REDADD(p, v) \
    asm volatile("red.global.add.f32 [%0], %1;" :: "l"(p), "f"(v) : "memory")
__device__ __forceinline__ uint32_t sm_u32(const void* p) {
    return (uint32_t)__cvta_generic_to_shared(p);
}

// ---------------------------------------------------------------------------
// zero: g_att (262144 float4) + g_l (16384 float4)
// ---------------------------------------------------------------------------
#define ZERO_TOT4 (262144 + 16384)   // 278528 = 1088 * 256
__global__ __launch_bounds__(256) void zero_kernel() {
    const int z = blockIdx.x * 256 + threadIdx.x;
    float4 zero = make_float4(0.f, 0.f, 0.f, 0.f);
    if (z < 262144) ((float4*)g_att)[z] = zero;
    else            ((float4*)g_l)[z - 262144] = zero;
}

// ---------------------------------------------------------------------------
// prepW: split the 4 weight matrices into bf16 hi/lo (vectorized)
// ---------------------------------------------------------------------------
#define PREPW_TOT4 (4*128*128/4)     // 16384 = 64 * 256
__global__ __launch_bounds__(256) void prepw_kernel(
    const float* __restrict__ Wk, const float* __restrict__ Wq,
    const float* __restrict__ Wv, const float* __restrict__ Wp)
{
    const int t4 = blockIdx.x * 256 + threadIdx.x;   // 0 .. 16383
    const int s = t4 >> 12, j = (t4 >> 5) & 127;
    const int k = (t4 & 31) * 4;
    const float* W = (s == 0) ? Wk : (s == 1) ? Wq : (s == 2) ? Wv : Wp;
    float4 v = *(const float4*)(W + j * 128 + k);
    __nv_bfloat16* dst = g_wb + (size_t)(s * 128 + j) * 256;

    uint32_t h0 = pack2(v.x, v.y);
    uint32_t h1 = pack2(v.z, v.w);
    uint32_t l0 = pack2(v.x - bflo(h0), v.y - bfhi(h0));
    uint32_t l1 = pack2(v.z - bflo(h1), v.w - bfhi(h1));
    *(uint2*)(dst + k)       = make_uint2(h0, h1);
    *(uint2*)(dst + 128 + k) = make_uint2(l0, l1);
}

// ---------------------------------------------------------------------------
// Tensor GEMM: out[row, j] = sum_k A[row,k] * W[j,k], 3-pass bf16 hi/lo HMMA.
// Block: 128 threads = 4 warps (2 row-groups x 2 col-groups), tile 32 rows.
// sel: -1 = QKV fused (blockIdx.y: 0=Q,1=K,2=V; A staged from fp32 x with
// inline hi/lo conversion), 3 = output projection with FUSED normalization
// (A resolved INSIDE the kernel from g_att / g_l; Aext unused).
// ---------------------------------------------------------------------------
#define APITCH 528   // 512B data + 16 pad; (4g+q4) mod 32 -> conflict-free frags

__global__ __launch_bounds__(128) void tgemm_kernel(
    const float* __restrict__ Aext, const float* __restrict__ bias,
    float* __restrict__ Oext, int selp)
{
    extern __shared__ char sm[];
    char* As = sm;                 // [32][528]
    char* Ws = sm + 32 * APITCH;   // [128][528]

    const int sel = (selp < 0) ? (int)blockIdx.y : selp;
    const int wsel = (sel == 0) ? 1 : (sel == 1) ? 0 : (sel == 2) ? 2 : 3;
    const __nv_bfloat16* Wsrc = g_wb + (size_t)wsel * 128 * 256;
    const float* Asel = (sel == 3) ? g_att : Aext;   // device-side symbol resolve

    const int tid = threadIdx.x;
    const int row0 = blockIdx.x * 32;

    // stage W (async from pre-split g_wb)
    #pragma unroll
    for (int i = tid; i < 4096; i += 128) {
        int r = i >> 5, c = i & 31;
        CP_ASYNC16(sm_u32(Ws + r * APITCH + c * 16),
                   (const char*)(Wsrc + (size_t)r * 256) + c * 16);
    }

    // stage A: fp32 source with inline hi/lo split
    #pragma unroll
    for (int i = tid; i < 1024; i += 128) {
        const int r = i >> 5, c = i & 31;       // c: float4 index in row
        const int row = row0 + r;
        float4 v = *(const float4*)(Asel + (size_t)row * CC + c * 4);
        float a0, a1, a2, a3;
        if (sel == 3) {
            const float inv = fast_rcp(g_l[row * HH + (c >> 2)]);
            a0 = v.x * inv; a1 = v.y * inv; a2 = v.z * inv; a3 = v.w * inv;
        } else {
            a0 = v.x; a1 = v.y; a2 = v.z; a3 = v.w;
        }
        uint32_t h0 = pack2(a0, a1);
        uint32_t h1 = pack2(a2, a3);
        uint32_t l0 = pack2(a0 - bflo(h0), a1 - bfhi(h0));
        uint32_t l1 = pack2(a2 - bflo(h1), a3 - bfhi(h1));
        *(uint2*)(As + r * APITCH + c * 8)       = make_uint2(h0, h1);
        *(uint2*)(As + r * APITCH + 256 + c * 8) = make_uint2(l0, l1);
    }
    CP_COMMIT(); CP_WAIT0();
    __syncthreads();

    const int wid = tid >> 5, lane = tid & 31;
    const int g = lane >> 2, q4 = lane & 3;
    const int rowg = wid >> 1, colg = wid & 1;

    float acc[8][4];
    #pragma unroll
    for (int nt = 0; nt < 8; ++nt)
        #pragma unroll
        for (int r = 0; r < 4; ++r) acc[nt][r] = 0.f;

    const char* Ab = As + (rowg * 16 + g) * APITCH;
    const char* Wb0 = Ws + (colg * 64 + g) * APITCH;

    #pragma unroll
    for (int kt = 0; kt < 8; ++kt) {
        const int ko = kt * 32 + q4 * 4;
        uint32_t ah[4], al[4];
        ah[0] = *(const uint32_t*)(Ab + ko);
        ah[1] = *(const uint32_t*)(Ab + 8 * APITCH + ko);
        ah[2] = *(const uint32_t*)(Ab + ko + 16);
        ah[3] = *(const uint32_t*)(Ab + 8 * APITCH + ko + 16);
        al[0] = *(const uint32_t*)(Ab + ko + 256);
        al[1] = *(const uint32_t*)(Ab + 8 * APITCH + ko + 256);
        al[2] = *(const uint32_t*)(Ab + ko + 272);
        al[3] = *(const uint32_t*)(Ab + 8 * APITCH + ko + 272);
        #pragma unroll
        for (int nt = 0; nt < 8; ++nt) {
            const char* wp = Wb0 + nt * 8 * APITCH + ko;
            uint32_t bh[2] = {*(const uint32_t*)(wp),       *(const uint32_t*)(wp + 16)};
            uint32_t bl[2] = {*(const uint32_t*)(wp + 256), *(const uint32_t*)(wp + 272)};
            mma16816(acc[nt], ah, bh);
            mma16816(acc[nt], al, bh);
            mma16816(acc[nt], ah, bl);
        }
    }

    const int r0 = row0 + rowg * 16 + g;
    const int b = r0 >> 12, t = r0 & (TT - 1);
    #pragma unroll
    for (int nt = 0; nt < 8; ++nt) {
        const int c = colg * 64 + nt * 8 + 2 * q4;
        if (sel == 3) {
            float2 bb = *(const float2*)(bias + c);
            *(float2*)(Oext + (size_t)r0 * 128 + c)       = make_float2(acc[nt][0] + bb.x, acc[nt][1] + bb.y);
            *(float2*)(Oext + (size_t)(r0 + 8) * 128 + c) = make_float2(acc[nt][2] + bb.x, acc[nt][3] + bb.y);
        } else {
            const int h = c >> 4, d = c & 15;
            if (sel == 2) {
                const size_t base = ((size_t)((b * HH + h) * DD + d)) * TT + t;
                __nv_bfloat16 h0 = __float2bfloat16_rn(acc[nt][0]);
                __nv_bfloat16 h1 = __float2bfloat16_rn(acc[nt][1]);
                __nv_bfloat16 h2 = __float2bfloat16_rn(acc[nt][2]);
                __nv_bfloat16 h3 = __float2bfloat16_rn(acc[nt][3]);
                g_vth[base]          = h0;
                g_vth[base + TT]     = h1;
                g_vth[base + 8]      = h2;
                g_vth[base + TT + 8] = h3;
                g_vtl[base]          = __float2bfloat16_rn(acc[nt][0] - __bfloat162float(h0));
                g_vtl[base + TT]     = __float2bfloat16_rn(acc[nt][1] - __bfloat162float(h1));
                g_vtl[base + 8]      = __float2bfloat16_rn(acc[nt][2] - __bfloat162float(h2));
                g_vtl[base + TT + 8] = __float2bfloat16_rn(acc[nt][3] - __bfloat162float(h3));
            } else {
                const size_t base = ((size_t)(b * HH + h) * TT + t) * DD + d;
                const float s = (sel == 0) ? 0.25f : 1.0f;
                __nv_bfloat16* dst = ((sel == 0) ? g_qb : g_kb) + base;
                *(uint32_t*)(dst)          = pack2(acc[nt][0] * s, acc[nt][1] * s);
                *(uint32_t*)(dst + 8 * DD) = pack2(acc[nt][2] * s, acc[nt][3] * s);
            }
        }
    }
}

// ---------------------------------------------------------------------------
// Split-K flash attention (R7 proven version). Block = (bh, qi, split);
// split covers <=4 key tiles. Partial O and l via red.global.add.
// ---------------------------------------------------------------------------
#define KPITCH 48
#define VPLANE 4352              // 16 * 272
#define VBUF   (2*VPLANE)        // 8704

__global__ __launch_bounds__(128, 4) void attn_kernel()
{
    __shared__ __align__(16) char ksm[2][128 * KPITCH];  // 12 KB
    __shared__ __align__(16) char vsm[2][VBUF];          // 17 KB

    const int tid  = threadIdx.x;
    const int wid  = tid >> 5;
    const int lane = tid & 31;
    const int g    = lane >> 2;
    const int q4   = lane & 3;
    const int bh   = blockIdx.y;

    // ---- map blockIdx.x (0..143) -> (qi, split) ----
    const int x = blockIdx.x;
    int a = (int)((sqrtf((float)(2 * x) + 1.0f) - 1.0f) * 0.5f);
    while (2 * (a + 1) * (a + 2) <= x) ++a;
    while (2 * a * (a + 1) > x) --a;
    const int r  = x - 2 * a * (a + 1);
    const int qi    = 4 * a + r / (a + 1);
    const int split = r % (a + 1);
    const int kt0   = 4 * split;
    const int ktend = (split == a) ? (qi + 1) : (kt0 + 4);

    // ---- Q fragments (bf16, pre-scaled) ----
    const __nv_bfloat16* Qb = g_qb + ((size_t)bh * TT + (size_t)qi * 128 + wid * 32) * DD;
    uint32_t qa[2][4];
    #pragma unroll
    for (int m = 0; m < 2; ++m) {
        const int r0 = 16 * m + g;
        qa[m][0] = *(const uint32_t*)(Qb + (size_t)r0 * DD + 2 * q4);
        qa[m][1] = *(const uint32_t*)(Qb + (size_t)(r0 + 8) * DD + 2 * q4);
        qa[m][2] = *(const uint32_t*)(Qb + (size_t)r0 * DD + 2 * q4 + 8);
        qa[m][3] = *(const uint32_t*)(Qb + (size_t)(r0 + 8) * DD + 2 * q4 + 8);
    }

    // O accumulators: [m][n 0..1 = V cols, 2 = ones column (row sums)]
    float O[2][3][4];
    #pragma unroll
    for (int m = 0; m < 2; ++m)
        #pragma unroll
        for (int n = 0; n < 3; ++n)
            #pragma unroll
            for (int rr = 0; rr < 4; ++rr) O[m][n][rr] = 0.f;

    const uint32_t vone = (g == 0) ? 0x3F803F80u : 0u;
    const uint32_t vones[2] = {vone, vone};

    const char* Kg  = (const char*)(g_kb  + ((size_t)bh * TT) * DD);
    const char* Vhg = (const char*)(g_vth + (size_t)bh * DD * TT);
    const char* Vlg = (const char*)(g_vtl + (size_t)bh * DD * TT);

    const int cid0 = tid * 4;

    // ---- stage first tile ----
    {
        uint32_t kd = sm_u32(&ksm[0][tid * KPITCH]);
        const char* ks = Kg + ((size_t)kt0 * 128 + tid) * 32;
        CP_ASYNC16(kd, ks); CP_ASYNC16(kd + 16, ks + 16);
        #pragma unroll
        for (int i = 0; i < 4; ++i) {
            const int cid = cid0 + i;
            const int pl = cid >> 8, d = (cid >> 4) & 15, ch = cid & 15;
            const char* src = (pl ? Vlg : Vhg) + ((size_t)d * TT + (size_t)kt0 * 128) * 2 + ch * 16;
            CP_ASYNC16(sm_u32(&vsm[0][pl * VPLANE + d * 272 + ch * 16]), src);
        }
        CP_COMMIT();
    }

    for (int kt = kt0; kt < ktend; ++kt) {
        const int buf = (kt - kt0) & 1;
        if (kt + 1 < ktend) {
            const int nb = buf ^ 1;
            uint32_t kd = sm_u32(&ksm[nb][tid * KPITCH]);
            const char* ks = Kg + ((size_t)(kt + 1) * 128 + tid) * 32;
            CP_ASYNC16(kd, ks); CP_ASYNC16(kd + 16, ks + 16);
            #pragma unroll
            for (int i = 0; i < 4; ++i) {
                const int cid = cid0 + i;
                const int pl = cid >> 8, d = (cid >> 4) & 15, ch = cid & 15;
                const char* src = (pl ? Vlg : Vhg) + ((size_t)d * TT + (size_t)(kt + 1) * 128) * 2 + ch * 16;
                CP_ASYNC16(sm_u32(&vsm[nb][pl * VPLANE + d * 272 + ch * 16]), src);
            }
            CP_COMMIT();
            CP_WAIT1();
        } else {
            CP_WAIT0();
        }
        __syncthreads();

        const char* kb_s = ksm[buf];
        const char* vhi  = vsm[buf];
        const char* vlo  = vsm[buf] + VPLANE;
        const bool diag = (kt == qi);
        const int nchunk = diag ? (wid + 1) : 4;

        for (int c = 0; c < nchunk; ++c) {
            const int kc = 32 * c;

            // K B-fragments
            uint32_t kb[4][2];
            #pragma unroll
            for (int nt = 0; nt < 4; ++nt) {
                const char* kp = kb_s + (kc + nt * 8 + g) * KPITCH + q4 * 4;
                kb[nt][0] = *(const uint32_t*)(kp);
                kb[nt][1] = *(const uint32_t*)(kp + 16);
            }

            // QK (single bf16 pass)
            float S[2][4][4];
            #pragma unroll
            for (int m = 0; m < 2; ++m)
                #pragma unroll
                for (int nt = 0; nt < 4; ++nt)
                    mma16816_init(S[m][nt], qa[m], kb[nt]);

            // softmax weights
            const bool dmask = diag && (c == wid);
            #pragma unroll
            for (int m = 0; m < 2; ++m) {
                const int ql0 = 32 * wid + 16 * m + g;
                #pragma unroll
                for (int nt = 0; nt < 4; ++nt) {
                    const int kl = kc + nt * 8 + 2 * q4;
                    float p0 = exp_poly(S[m][nt][0]);
                    float p1 = exp_poly(S[m][nt][1]);
                    float p2 = exp_poly(S[m][nt][2]);
                    float p3 = exp_poly(S[m][nt][3]);
                    if (dmask) {
                        if (kl     > ql0)     p0 = 0.f;
                        if (kl + 1 > ql0)     p1 = 0.f;
                        if (kl     > ql0 + 8) p2 = 0.f;
                        if (kl + 1 > ql0 + 8) p3 = 0.f;
                    }
                    S[m][nt][0] = p0; S[m][nt][1] = p1;
                    S[m][nt][2] = p2; S[m][nt][3] = p3;
                }
            }

            // pack P hi/lo A-fragments
            uint32_t ph[2][2][4], pl[2][2][4];
            #pragma unroll
            for (int m = 0; m < 2; ++m)
                #pragma unroll
                for (int s = 0; s < 2; ++s) {
                    const float* t0 = S[m][2 * s];
                    const float* t1 = S[m][2 * s + 1];
                    ph[m][s][0] = pack2(t0[0], t0[1]);
                    ph[m][s][1] = pack2(t0[2], t0[3]);
                    ph[m][s][2] = pack2(t1[0], t1[1]);
                    ph[m][s][3] = pack2(t1[2], t1[3]);
                    pl[m][s][0] = pack2(t0[0] - bflo(ph[m][s][0]), t0[1] - bfhi(ph[m][s][0]));
                    pl[m][s][1] = pack2(t0[2] - bflo(ph[m][s][1]), t0[3] - bfhi(ph[m][s][1]));
                    pl[m][s][2] = pack2(t1[0] - bflo(ph[m][s][2]), t1[1] - bfhi(ph[m][s][2]));
                    pl[m][s][3] = pack2(t1[2] - bflo(ph[m][s][3]), t1[3] - bfhi(ph[m][s][3]));
                }

            // V B-fragments: direct LDS.32 from pre-split planes
            uint32_t vh[2][2][2], vl[2][2][2];
            #pragma unroll
            for (int s = 0; s < 2; ++s)
                #pragma unroll
                for (int nt = 0; nt < 2; ++nt) {
                    const int off = (nt * 8 + g) * 272 + (kc + 16 * s + 2 * q4) * 2;
                    vh[s][nt][0] = *(const uint32_t*)(vhi + off);
                    vh[s][nt][1] = *(const uint32_t*)(vhi + off + 16);
                    vl[s][nt][0] = *(const uint32_t*)(vlo + off);
                    vl[s][nt][1] = *(const uint32_t*)(vlo + off + 16);
                }

            // PV (+ones for row sums)
            #pragma unroll
            for (int m = 0; m < 2; ++m)
                #pragma unroll
                for (int s = 0; s < 2; ++s) {
                    mma16816(O[m][0], ph[m][s], vh[s][0]);
                    mma16816(O[m][1], ph[m][s], vh[s][1]);
                    mma16816(O[m][2], ph[m][s], vones);
                    mma16816(O[m][0], pl[m][s], vh[s][0]);
                    mma16816(O[m][1], pl[m][s], vh[s][1]);
                    mma16816(O[m][2], pl[m][s], vones);
                    mma16816(O[m][0], ph[m][s], vl[s][0]);
                    mma16816(O[m][1], ph[m][s], vl[s][1]);
                }
        }
        __syncthreads();
    }

    // ---- epilogue: atomic accumulate partial O and l ----
    const int b = bh >> 3, h = bh & 7;
    #pragma unroll
    for (int m = 0; m < 2; ++m) {
        const int row0 = qi * 128 + 32 * wid + 16 * m + g;
        if (q4 == 0) {
            REDADD(&g_l[(size_t)(b * TT + row0) * HH + h],     O[m][2][0]);
            REDADD(&g_l[(size_t)(b * TT + row0 + 8) * HH + h], O[m][2][2]);
        }
        #pragma unroll
        for (int nt = 0; nt < 2; ++nt) {
            const int d = nt * 8 + 2 * q4;
            float* p0 = g_att + (size_t)(b * TT + row0) * CC + h * DD + d;
            float* p1 = g_att + (size_t)(b * TT + row0 + 8) * CC + h * DD + d;
            REDADD(p0,     O[m][nt][0]);
            REDADD(p0 + 1, O[m][nt][1]);
            REDADD(p1,     O[m][nt][2]);
            REDADD(p1 + 1, O[m][nt][3]);
        }
    }
}

// ---------------------------------------------------------------------------
// Launch: zero(1) -> prepW(2) -> QKV tgemm(3) -> attn(4) -> proj tgemm(5)
// (attn at position 4 so the profiler's 4th-launch capture lands on it)
// inputs (metadata order): x, Wk, Wq, Wv, Wp, bp
// ---------------------------------------------------------------------------
extern "C" void kernel_launch(void* const* d_in, const int* in_sizes, int n_in,
                              void* d_out, int out_size)
{
    const float* x  = (const float*)d_in[0];
    const float* Wk = (const float*)d_in[1];
    const float* Wq = (const float*)d_in[2];
    const float* Wv = (const float*)d_in[3];
    const float* Wp = (const float*)d_in[4];
    const float* bp = (const float*)d_in[5];
    float* out = (float*)d_out;

    const int tg_smem = 32 * APITCH + 128 * APITCH;  // 84480
    cudaFuncSetAttribute(tgemm_kernel, cudaFuncAttributeMaxDynamicSharedMemorySize, tg_smem);

    zero_kernel<<<ZERO_TOT4 / 256, 256>>>();
    prepw_kernel<<<PREPW_TOT4 / 256, 256>>>(Wk, Wq, Wv, Wp);

    dim3 qkv_grid(256, 3);
    tgemm_kernel<<<qkv_grid, 128, tg_smem>>>(x, nullptr, nullptr, -1);  // Q,K,V fused

    dim3 agrid(144, NBH);
    attn_kernel<<<agrid, 128>>>();

    tgemm_kernel<<<256, 128, tg_smem>>>(nullptr, bp, out, 3);  // proj + fused norm
}

// round 14
// speedup vs baseline: 1.0700x; 1.0700x over previous
#include <cuda_runtime.h>
#include <cuda_bf16.h>
#include <cstdint>

// Problem constants
#define BB 2
#define TT 4096
#define CC 128
#define HH 8
#define DD 16
#define MROWS (BB*TT)          // 8192
#define NBH (BB*HH)            // 16

// Scratch (device globals; no allocation allowed)
__device__ __nv_bfloat16 g_xb[MROWS*256];    // [row][hi128|lo128]
__device__ __nv_bfloat16 g_wb[4*128*256];    // [sel][j][hi128|lo128] (Wk,Wq,Wv,Wp)
__device__ __nv_bfloat16 g_qb[NBH*TT*DD];    // [bh][t][16] bf16 (pre-scaled 0.25*log2e)
__device__ __nv_bfloat16 g_kb[NBH*TT*DD];    // [bh][t][16] bf16
__device__ __nv_bfloat16 g_vth[NBH*DD*TT];   // V hi, transposed: [bh*16+d][t]
__device__ __nv_bfloat16 g_vtl[NBH*DD*TT];   // V lo, transposed: [bh*16+d][t]
__device__ float g_att[MROWS*CC];            // unnormalized attn accum (atomic)
__device__ float g_l[MROWS*HH];              // row sums (atomic)

// ============================================================================
// Helpers
// ============================================================================
__device__ __forceinline__ void mma16816(float d[4], const uint32_t a[4], const uint32_t b[2]) {
    asm volatile("mma.sync.aligned.m16n8k16.row.col.f32.bf16.bf16.f32 "
        "{%0,%1,%2,%3}, {%4,%5,%6,%7}, {%8,%9}, {%0,%1,%2,%3};"
        : "+f"(d[0]), "+f"(d[1]), "+f"(d[2]), "+f"(d[3])
        : "r"(a[0]), "r"(a[1]), "r"(a[2]), "r"(a[3]), "r"(b[0]), "r"(b[1]));
}
__device__ __forceinline__ void mma16816_init(float d[4], const uint32_t a[4], const uint32_t b[2]) {
    asm volatile("mma.sync.aligned.m16n8k16.row.col.f32.bf16.bf16.f32 "
        "{%0,%1,%2,%3}, {%4,%5,%6,%7}, {%8,%9}, {%10,%10,%10,%10};"
        : "=f"(d[0]), "=f"(d[1]), "=f"(d[2]), "=f"(d[3])
        : "r"(a[0]), "r"(a[1]), "r"(a[2]), "r"(a[3]), "r"(b[0]), "r"(b[1]), "f"(0.0f));
}
__device__ __forceinline__ uint32_t pack2(float lo_el, float hi_el) {
    __nv_bfloat162 h = __floats2bfloat162_rn(lo_el, hi_el);
    return *reinterpret_cast<uint32_t*>(&h);
}
__device__ __forceinline__ float bflo(uint32_t u) { uint32_t v = u << 16;         return __uint_as_float(v); }
__device__ __forceinline__ float bfhi(uint32_t u) { uint32_t v = u & 0xFFFF0000u; return __uint_as_float(v); }
__device__ __forceinline__ float ex2f(float x) {   // p = 2^x (scale pre-folded into Q)
    float r; asm("ex2.approx.ftz.f32 %0, %1;" : "=f"(r) : "f"(x)); return r;
}
__device__ __forceinline__ float fast_rcp(float x) {
    float r; asm("rcp.approx.f32 %0, %1;" : "=f"(r) : "f"(x));
    return r * (2.0f - x * r);   // one Newton step
}
#define CP_ASYNC16(dst_u32, src_ptr) \
    asm volatile("cp.async.ca.shared.global [%0], [%1], 16;" :: "r"(dst_u32), "l"(src_ptr))
#define CP_COMMIT() asm volatile("cp.async.commit_group;" ::: "memory")
#define CP_WAIT0()  asm volatile("cp.async.wait_group 0;" ::: "memory")
#define CP_WAIT1()  asm volatile("cp.async.wait_group 1;" ::: "memory")
#define REDADD(p, v) \
    asm volatile("red.global.add.f32 [%0], %1;" :: "l"(p), "f"(v) : "memory")
__device__ __forceinline__ uint32_t sm_u32(const void* p) {
    return (uint32_t)__cvta_generic_to_shared(p);
}

// ---------------------------------------------------------------------------
// prep (vectorized, R10-proven): split x and 4 W matrices into bf16 hi/lo
// (4 floats per thread: 1x LDG.128, 2x 8B STG), and zero g_att / g_l.
// ---------------------------------------------------------------------------
#define PREP_X4  (MROWS*CC/4)              // 262144 float4 of x
#define PREP_W4  (4*128*128/4)             // 16384 float4 of W
#define PREP_Z4  (262144 + 16384)          // float4 count for g_att + g_l
#define PREP_TOT4 (PREP_X4 + PREP_W4 + PREP_Z4)   // 557056 = 2176 * 256

__global__ __launch_bounds__(256) void prep_kernel(
    const float* __restrict__ x,
    const float* __restrict__ Wk, const float* __restrict__ Wq,
    const float* __restrict__ Wv, const float* __restrict__ Wp)
{
    const int idx4 = blockIdx.x * 256 + threadIdx.x;
    if (idx4 >= PREP_X4 + PREP_W4) {
        const int z = idx4 - (PREP_X4 + PREP_W4);
        float4 zero = make_float4(0.f, 0.f, 0.f, 0.f);
        if (z < 262144) ((float4*)g_att)[z] = zero;
        else            ((float4*)g_l)[z - 262144] = zero;
        return;
    }

    float4 v;
    __nv_bfloat16* dst;  // row base; hi at [k..k+3], lo at [128+k..]
    int k;
    if (idx4 < PREP_X4) {
        const int row = idx4 >> 5;
        k = (idx4 & 31) * 4;
        v = ((const float4*)x)[idx4];
        dst = g_xb + (size_t)row * 256;
    } else {
        const int t4 = idx4 - PREP_X4;           // 0 .. 16383
        const int s = t4 >> 12, j = (t4 >> 5) & 127;
        k = (t4 & 31) * 4;
        const float* W = (s == 0) ? Wk : (s == 1) ? Wq : (s == 2) ? Wv : Wp;
        v = *(const float4*)(W + j * 128 + k);
        dst = g_wb + (size_t)(s * 128 + j) * 256;
    }

    uint32_t h0 = pack2(v.x, v.y);
    uint32_t h1 = pack2(v.z, v.w);
    uint32_t l0 = pack2(v.x - bflo(h0), v.y - bfhi(h0));
    uint32_t l1 = pack2(v.z - bflo(h1), v.w - bfhi(h1));
    *(uint2*)(dst + k)       = make_uint2(h0, h1);
    *(uint2*)(dst + 128 + k) = make_uint2(l0, l1);
}

// ---------------------------------------------------------------------------
// Tensor GEMM: out[row, j] = sum_k A[row,k] * W[j,k], 3-pass bf16 hi/lo HMMA.
// Block: 128 threads = 4 warps (2 row-groups x 2 col-groups), tile 32 rows.
// sel: -1 = QKV fused (blockIdx.y: 0=Q,1=K,2=V; A cp.async from g_xb),
//      3 = output projection with FUSED normalization (A from g_att / g_l).
// Q epilogue scale = 0.25 * log2(e): scores land in log2 domain -> exp = ex2.
// ---------------------------------------------------------------------------
#define APITCH 528   // 512B data + 16 pad; (4g+q4) mod 32 -> conflict-free frags
#define QSCALE 0.36067376f   // 0.25 * 1.4426950408889634

__global__ __launch_bounds__(128) void tgemm_kernel(
    const float* __restrict__ bias, float* __restrict__ Oext, int selp)
{
    extern __shared__ char sm[];
    char* As = sm;                 // [32][528]
    char* Ws = sm + 32 * APITCH;   // [128][528]

    const int sel = (selp < 0) ? (int)blockIdx.y : selp;
    const int wsel = (sel == 0) ? 1 : (sel == 1) ? 0 : (sel == 2) ? 2 : 3;
    const __nv_bfloat16* Wsrc = g_wb + (size_t)wsel * 128 * 256;

    const int tid = threadIdx.x;
    const int row0 = blockIdx.x * 32;

    // stage W (async from pre-split g_wb)
    #pragma unroll
    for (int i = tid; i < 4096; i += 128) {
        int r = i >> 5, c = i & 31;
        CP_ASYNC16(sm_u32(Ws + r * APITCH + c * 16),
                   (const char*)(Wsrc + (size_t)r * 256) + c * 16);
    }

    // stage A
    if (sel == 3) {
        // fused normalize + split from g_att / g_l
        #pragma unroll
        for (int i = tid; i < 1024; i += 128) {
            const int r = i >> 5, c = i & 31;       // c: float4 index in row
            const int row = row0 + r;
            float4 v = *(const float4*)(g_att + (size_t)row * CC + c * 4);
            const float inv = fast_rcp(g_l[row * HH + (c >> 2)]);
            float a0 = v.x * inv, a1 = v.y * inv, a2 = v.z * inv, a3 = v.w * inv;
            uint32_t h0 = pack2(a0, a1);
            uint32_t h1 = pack2(a2, a3);
            uint32_t l0 = pack2(a0 - bflo(h0), a1 - bfhi(h0));
            uint32_t l1 = pack2(a2 - bflo(h1), a3 - bfhi(h1));
            *(uint2*)(As + r * APITCH + c * 8)       = make_uint2(h0, h1);
            *(uint2*)(As + r * APITCH + 256 + c * 8) = make_uint2(l0, l1);
        }
    } else {
        #pragma unroll
        for (int i = tid; i < 1024; i += 128) {
            int r = i >> 5, c = i & 31;
            CP_ASYNC16(sm_u32(As + r * APITCH + c * 16),
                       (const char*)(g_xb + (size_t)(row0 + r) * 256) + c * 16);
        }
    }
    CP_COMMIT(); CP_WAIT0();
    __syncthreads();

    const int wid = tid >> 5, lane = tid & 31;
    const int g = lane >> 2, q4 = lane & 3;
    const int rowg = wid >> 1, colg = wid & 1;

    float acc[8][4];
    #pragma unroll
    for (int nt = 0; nt < 8; ++nt)
        #pragma unroll
        for (int r = 0; r < 4; ++r) acc[nt][r] = 0.f;

    const char* Ab = As + (rowg * 16 + g) * APITCH;
    const char* Wb0 = Ws + (colg * 64 + g) * APITCH;

    #pragma unroll
    for (int kt = 0; kt < 8; ++kt) {
        const int ko = kt * 32 + q4 * 4;
        uint32_t ah[4], al[4];
        ah[0] = *(const uint32_t*)(Ab + ko);
        ah[1] = *(const uint32_t*)(Ab + 8 * APITCH + ko);
        ah[2] = *(const uint32_t*)(Ab + ko + 16);
        ah[3] = *(const uint32_t*)(Ab + 8 * APITCH + ko + 16);
        al[0] = *(const uint32_t*)(Ab + ko + 256);
        al[1] = *(const uint32_t*)(Ab + 8 * APITCH + ko + 256);
        al[2] = *(const uint32_t*)(Ab + ko + 272);
        al[3] = *(const uint32_t*)(Ab + 8 * APITCH + ko + 272);
        #pragma unroll
        for (int nt = 0; nt < 8; ++nt) {
            const char* wp = Wb0 + nt * 8 * APITCH + ko;
            uint32_t bh[2] = {*(const uint32_t*)(wp),       *(const uint32_t*)(wp + 16)};
            uint32_t bl[2] = {*(const uint32_t*)(wp + 256), *(const uint32_t*)(wp + 272)};
            mma16816(acc[nt], ah, bh);
            mma16816(acc[nt], al, bh);
            mma16816(acc[nt], ah, bl);
        }
    }

    const int r0 = row0 + rowg * 16 + g;
    const int b = r0 >> 12, t = r0 & (TT - 1);
    #pragma unroll
    for (int nt = 0; nt < 8; ++nt) {
        const int c = colg * 64 + nt * 8 + 2 * q4;
        if (sel == 3) {
            float2 bb = *(const float2*)(bias + c);
            *(float2*)(Oext + (size_t)r0 * 128 + c)       = make_float2(acc[nt][0] + bb.x, acc[nt][1] + bb.y);
            *(float2*)(Oext + (size_t)(r0 + 8) * 128 + c) = make_float2(acc[nt][2] + bb.x, acc[nt][3] + bb.y);
        } else {
            const int h = c >> 4, d = c & 15;
            if (sel == 2) {
                const size_t base = ((size_t)((b * HH + h) * DD + d)) * TT + t;
                __nv_bfloat16 h0 = __float2bfloat16_rn(acc[nt][0]);
                __nv_bfloat16 h1 = __float2bfloat16_rn(acc[nt][1]);
                __nv_bfloat16 h2 = __float2bfloat16_rn(acc[nt][2]);
                __nv_bfloat16 h3 = __float2bfloat16_rn(acc[nt][3]);
                g_vth[base]          = h0;
                g_vth[base + TT]     = h1;
                g_vth[base + 8]      = h2;
                g_vth[base + TT + 8] = h3;
                g_vtl[base]          = __float2bfloat16_rn(acc[nt][0] - __bfloat162float(h0));
                g_vtl[base + TT]     = __float2bfloat16_rn(acc[nt][1] - __bfloat162float(h1));
                g_vtl[base + 8]      = __float2bfloat16_rn(acc[nt][2] - __bfloat162float(h2));
                g_vtl[base + TT + 8] = __float2bfloat16_rn(acc[nt][3] - __bfloat162float(h3));
            } else {
                const size_t base = ((size_t)(b * HH + h) * TT + t) * DD + d;
                const float s = (sel == 0) ? QSCALE : 1.0f;
                __nv_bfloat16* dst = ((sel == 0) ? g_qb : g_kb) + base;
                *(uint32_t*)(dst)          = pack2(acc[nt][0] * s, acc[nt][1] * s);
                *(uint32_t*)(dst + 8 * DD) = pack2(acc[nt][2] * s, acc[nt][3] * s);
            }
        }
    }
}

// ---------------------------------------------------------------------------
// Split-K flash attention. Block = (bh, qi, split); split covers <=4 key tiles.
// exp via MUFU ex2 (log2-domain scores, scale folded into Q projection).
// Partial O and l via red.global.add.
// ---------------------------------------------------------------------------
#define KPITCH 48
#define VPLANE 4352              // 16 * 272
#define VBUF   (2*VPLANE)        // 8704

__global__ __launch_bounds__(128, 4) void attn_kernel()
{
    __shared__ __align__(16) char ksm[2][128 * KPITCH];  // 12 KB
    __shared__ __align__(16) char vsm[2][VBUF];          // 17 KB

    const int tid  = threadIdx.x;
    const int wid  = tid >> 5;
    const int lane = tid & 31;
    const int g    = lane >> 2;
    const int q4   = lane & 3;
    const int bh   = blockIdx.y;

    // ---- map blockIdx.x (0..143) -> (qi, split) ----
    const int x = blockIdx.x;
    int a = (int)((sqrtf((float)(2 * x) + 1.0f) - 1.0f) * 0.5f);
    while (2 * (a + 1) * (a + 2) <= x) ++a;
    while (2 * a * (a + 1) > x) --a;
    const int r  = x - 2 * a * (a + 1);
    const int qi    = 4 * a + r / (a + 1);
    const int split = r % (a + 1);
    const int kt0   = 4 * split;
    const int ktend = (split == a) ? (qi + 1) : (kt0 + 4);

    // ---- Q fragments (bf16, pre-scaled by 0.25*log2e) ----
    const __nv_bfloat16* Qb = g_qb + ((size_t)bh * TT + (size_t)qi * 128 + wid * 32) * DD;
    uint32_t qa[2][4];
    #pragma unroll
    for (int m = 0; m < 2; ++m) {
        const int r0 = 16 * m + g;
        qa[m][0] = *(const uint32_t*)(Qb + (size_t)r0 * DD + 2 * q4);
        qa[m][1] = *(const uint32_t*)(Qb + (size_t)(r0 + 8) * DD + 2 * q4);
        qa[m][2] = *(const uint32_t*)(Qb + (size_t)r0 * DD + 2 * q4 + 8);
        qa[m][3] = *(const uint32_t*)(Qb + (size_t)(r0 + 8) * DD + 2 * q4 + 8);
    }

    // O accumulators: [m][n 0..1 = V cols, 2 = ones column (row sums)]
    float O[2][3][4];
    #pragma unroll
    for (int m = 0; m < 2; ++m)
        #pragma unroll
        for (int n = 0; n < 3; ++n)
            #pragma unroll
            for (int rr = 0; rr < 4; ++rr) O[m][n][rr] = 0.f;

    const uint32_t vone = (g == 0) ? 0x3F803F80u : 0u;
    const uint32_t vones[2] = {vone, vone};

    const char* Kg  = (const char*)(g_kb  + ((size_t)bh * TT) * DD);
    const char* Vhg = (const char*)(g_vth + (size_t)bh * DD * TT);
    const char* Vlg = (const char*)(g_vtl + (size_t)bh * DD * TT);

    const int cid0 = tid * 4;

    // ---- stage first tile ----
    {
        uint32_t kd = sm_u32(&ksm[0][tid * KPITCH]);
        const char* ks = Kg + ((size_t)kt0 * 128 + tid) * 32;
        CP_ASYNC16(kd, ks); CP_ASYNC16(kd + 16, ks + 16);
        #pragma unroll
        for (int i = 0; i < 4; ++i) {
            const int cid = cid0 + i;
            const int pl = cid >> 8, d = (cid >> 4) & 15, ch = cid & 15;
            const char* src = (pl ? Vlg : Vhg) + ((size_t)d * TT + (size_t)kt0 * 128) * 2 + ch * 16;
            CP_ASYNC16(sm_u32(&vsm[0][pl * VPLANE + d * 272 + ch * 16]), src);
        }
        CP_COMMIT();
    }

    for (int kt = kt0; kt < ktend; ++kt) {
        const int buf = (kt - kt0) & 1;
        if (kt + 1 < ktend) {
            const int nb = buf ^ 1;
            uint32_t kd = sm_u32(&ksm[nb][tid * KPITCH]);
            const char* ks = Kg + ((size_t)(kt + 1) * 128 + tid) * 32;
            CP_ASYNC16(kd, ks); CP_ASYNC16(kd + 16, ks + 16);
            #pragma unroll
            for (int i = 0; i < 4; ++i) {
                const int cid = cid0 + i;
                const int pl = cid >> 8, d = (cid >> 4) & 15, ch = cid & 15;
                const char* src = (pl ? Vlg : Vhg) + ((size_t)d * TT + (size_t)(kt + 1) * 128) * 2 + ch * 16;
                CP_ASYNC16(sm_u32(&vsm[nb][pl * VPLANE + d * 272 + ch * 16]), src);
            }
            CP_COMMIT();
            CP_WAIT1();
        } else {
            CP_WAIT0();
        }
        __syncthreads();

        const char* kb_s = ksm[buf];
        const char* vhi  = vsm[buf];
        const char* vlo  = vsm[buf] + VPLANE;
        const bool diag = (kt == qi);
        const int nchunk = diag ? (wid + 1) : 4;

        for (int c = 0; c < nchunk; ++c) {
            const int kc = 32 * c;

            // K B-fragments
            uint32_t kb[4][2];
            #pragma unroll
            for (int nt = 0; nt < 4; ++nt) {
                const char* kp = kb_s + (kc + nt * 8 + g) * KPITCH + q4 * 4;
                kb[nt][0] = *(const uint32_t*)(kp);
                kb[nt][1] = *(const uint32_t*)(kp + 16);
            }

            // QK (single bf16 pass; scores in log2 domain)
            float S[2][4][4];
            #pragma unroll
            for (int m = 0; m < 2; ++m)
                #pragma unroll
                for (int nt = 0; nt < 4; ++nt)
                    mma16816_init(S[m][nt], qa[m], kb[nt]);

            // softmax weights: p = 2^s via MUFU (idle pipe)
            const bool dmask = diag && (c == wid);
            #pragma unroll
            for (int m = 0; m < 2; ++m) {
                const int ql0 = 32 * wid + 16 * m + g;
                #pragma unroll
                for (int nt = 0; nt < 4; ++nt) {
                    const int kl = kc + nt * 8 + 2 * q4;
                    float p0 = ex2f(S[m][nt][0]);
                    float p1 = ex2f(S[m][nt][1]);
                    float p2 = ex2f(S[m][nt][2]);
                    float p3 = ex2f(S[m][nt][3]);
                    if (dmask) {
                        if (kl     > ql0)     p0 = 0.f;
                        if (kl + 1 > ql0)     p1 = 0.f;
                        if (kl     > ql0 + 8) p2 = 0.f;
                        if (kl + 1 > ql0 + 8) p3 = 0.f;
                    }
                    S[m][nt][0] = p0; S[m][nt][1] = p1;
                    S[m][nt][2] = p2; S[m][nt][3] = p3;
                }
            }

            // pack P hi/lo A-fragments
            uint32_t ph[2][2][4], pl[2][2][4];
            #pragma unroll
            for (int m = 0; m < 2; ++m)
                #pragma unroll
                for (int s = 0; s < 2; ++s) {
                    const float* t0 = S[m][2 * s];
                    const float* t1 = S[m][2 * s + 1];
                    ph[m][s][0] = pack2(t0[0], t0[1]);
                    ph[m][s][1] = pack2(t0[2], t0[3]);
                    ph[m][s][2] = pack2(t1[0], t1[1]);
                    ph[m][s][3] = pack2(t1[2], t1[3]);
                    pl[m][s][0] = pack2(t0[0] - bflo(ph[m][s][0]), t0[1] - bfhi(ph[m][s][0]));
                    pl[m][s][1] = pack2(t0[2] - bflo(ph[m][s][1]), t0[3] - bfhi(ph[m][s][1]));
                    pl[m][s][2] = pack2(t1[0] - bflo(ph[m][s][2]), t1[1] - bfhi(ph[m][s][2]));
                    pl[m][s][3] = pack2(t1[2] - bflo(ph[m][s][3]), t1[3] - bfhi(ph[m][s][3]));
                }

            // V B-fragments: direct LDS.32 from pre-split planes
            uint32_t vh[2][2][2], vl[2][2][2];
            #pragma unroll
            for (int s = 0; s < 2; ++s)
                #pragma unroll
                for (int nt = 0; nt < 2; ++nt) {
                    const int off = (nt * 8 + g) * 272 + (kc + 16 * s + 2 * q4) * 2;
                    vh[s][nt][0] = *(const uint32_t*)(vhi + off);
                    vh[s][nt][1] = *(const uint32_t*)(vhi + off + 16);
                    vl[s][nt][0] = *(const uint32_t*)(vlo + off);
                    vl[s][nt][1] = *(const uint32_t*)(vlo + off + 16);
                }

            // PV (+ones for row sums)
            #pragma unroll
            for (int m = 0; m < 2; ++m)
                #pragma unroll
                for (int s = 0; s < 2; ++s) {
                    mma16816(O[m][0], ph[m][s], vh[s][0]);
                    mma16816(O[m][1], ph[m][s], vh[s][1]);
                    mma16816(O[m][2], ph[m][s], vones);
                    mma16816(O[m][0], pl[m][s], vh[s][0]);
                    mma16816(O[m][1], pl[m][s], vh[s][1]);
                    mma16816(O[m][2], pl[m][s], vones);
                    mma16816(O[m][0], ph[m][s], vl[s][0]);
                    mma16816(O[m][1], ph[m][s], vl[s][1]);
                }
        }
        __syncthreads();
    }

    // ---- epilogue: atomic accumulate partial O and l ----
    const int b = bh >> 3, h = bh & 7;
    #pragma unroll
    for (int m = 0; m < 2; ++m) {
        const int row0 = qi * 128 + 32 * wid + 16 * m + g;
        if (q4 == 0) {
            REDADD(&g_l[(size_t)(b * TT + row0) * HH + h],     O[m][2][0]);
            REDADD(&g_l[(size_t)(b * TT + row0 + 8) * HH + h], O[m][2][2]);
        }
        #pragma unroll
        for (int nt = 0; nt < 2; ++nt) {
            const int d = nt * 8 + 2 * q4;
            float* p0 = g_att + (size_t)(b * TT + row0) * CC + h * DD + d;
            float* p1 = g_att + (size_t)(b * TT + row0 + 8) * CC + h * DD + d;
            REDADD(p0,     O[m][nt][0]);
            REDADD(p0 + 1, O[m][nt][1]);
            REDADD(p1,     O[m][nt][2]);
            REDADD(p1 + 1, O[m][nt][3]);
        }
    }
}

// ---------------------------------------------------------------------------
// Launch: prep(+zero) -> fused QKV tgemm -> attention -> proj tgemm (fused norm)
// inputs (metadata order): x, Wk, Wq, Wv, Wp, bp
// ---------------------------------------------------------------------------
extern "C" void kernel_launch(void* const* d_in, const int* in_sizes, int n_in,
                              void* d_out, int out_size)
{
    const float* x  = (const float*)d_in[0];
    const float* Wk = (const float*)d_in[1];
    const float* Wq = (const float*)d_in[2];
    const float* Wv = (const float*)d_in[3];
    const float* Wp = (const float*)d_in[4];
    const float* bp = (const float*)d_in[5];
    float* out = (float*)d_out;

    const int tg_smem = 32 * APITCH + 128 * APITCH;  // 84480
    cudaFuncSetAttribute(tgemm_kernel, cudaFuncAttributeMaxDynamicSharedMemorySize, tg_smem);

    prep_kernel<<<PREP_TOT4 / 256, 256>>>(x, Wk, Wq, Wv, Wp);

    dim3 qkv_grid(256, 3);
    tgemm_kernel<<<qkv_grid, 128, tg_smem>>>(nullptr, nullptr, -1);  // Q,K,V fused

    dim3 agrid(144, NBH);
    attn_kernel<<<agrid, 128>>>();

    tgemm_kernel<<<256, 128, tg_smem>>>(bp, out, 3);  // proj + fused norm
}

// round 15
// speedup vs baseline: 1.0794x; 1.0087x over previous
#include <cuda_runtime.h>
#include <cuda_bf16.h>
#include <cstdint>

// Problem constants
#define BB 2
#define TT 4096
#define CC 128
#define HH 8
#define DD 16
#define MROWS (BB*TT)          // 8192
#define NBH (BB*HH)            // 16

// Scratch (device globals; no allocation allowed)
__device__ __nv_bfloat16 g_xb[MROWS*256];    // [row][hi128|lo128]
__device__ __nv_bfloat16 g_wb[4*128*256];    // [sel][j][hi128|lo128] (Wk,Wq,Wv,Wp)
__device__ __nv_bfloat16 g_qb[NBH*TT*DD];    // [bh][t][16] bf16 (pre-scaled 0.25*log2e)
__device__ __nv_bfloat16 g_kb[NBH*TT*DD];    // [bh][t][16] bf16
__device__ __nv_bfloat16 g_vth[NBH*DD*TT];   // V hi, transposed: [bh*16+d][t]
__device__ __nv_bfloat16 g_vtl[NBH*DD*TT];   // V lo, transposed: [bh*16+d][t]
__device__ float g_att[MROWS*CC];            // unnormalized attn accum (atomic)
__device__ float g_l[MROWS*HH];              // row sums (atomic)

// ============================================================================
// Helpers
// ============================================================================
__device__ __forceinline__ void mma16816(float d[4], const uint32_t a[4], const uint32_t b[2]) {
    asm volatile("mma.sync.aligned.m16n8k16.row.col.f32.bf16.bf16.f32 "
        "{%0,%1,%2,%3}, {%4,%5,%6,%7}, {%8,%9}, {%0,%1,%2,%3};"
        : "+f"(d[0]), "+f"(d[1]), "+f"(d[2]), "+f"(d[3])
        : "r"(a[0]), "r"(a[1]), "r"(a[2]), "r"(a[3]), "r"(b[0]), "r"(b[1]));
}
__device__ __forceinline__ void mma16816_init(float d[4], const uint32_t a[4], const uint32_t b[2]) {
    asm volatile("mma.sync.aligned.m16n8k16.row.col.f32.bf16.bf16.f32 "
        "{%0,%1,%2,%3}, {%4,%5,%6,%7}, {%8,%9}, {%10,%10,%10,%10};"
        : "=f"(d[0]), "=f"(d[1]), "=f"(d[2]), "=f"(d[3])
        : "r"(a[0]), "r"(a[1]), "r"(a[2]), "r"(a[3]), "r"(b[0]), "r"(b[1]), "f"(0.0f));
}
__device__ __forceinline__ uint32_t pack2(float lo_el, float hi_el) {
    __nv_bfloat162 h = __floats2bfloat162_rn(lo_el, hi_el);
    return *reinterpret_cast<uint32_t*>(&h);
}
__device__ __forceinline__ float bflo(uint32_t u) { uint32_t v = u << 16;         return __uint_as_float(v); }
__device__ __forceinline__ float bfhi(uint32_t u) { uint32_t v = u & 0xFFFF0000u; return __uint_as_float(v); }
__device__ __forceinline__ float ex2f(float x) {   // p = 2^x (scale pre-folded into Q)
    float r; asm("ex2.approx.ftz.f32 %0, %1;" : "=f"(r) : "f"(x)); return r;
}
__device__ __forceinline__ float fast_rcp(float x) {
    float r; asm("rcp.approx.f32 %0, %1;" : "=f"(r) : "f"(x));
    return r * (2.0f - x * r);   // one Newton step
}
#define CP_ASYNC16(dst_u32, src_ptr) \
    asm volatile("cp.async.ca.shared.global [%0], [%1], 16;" :: "r"(dst_u32), "l"(src_ptr))
#define CP_COMMIT() asm volatile("cp.async.commit_group;" ::: "memory")
#define CP_WAIT0()  asm volatile("cp.async.wait_group 0;" ::: "memory")
#define CP_WAIT1()  asm volatile("cp.async.wait_group 1;" ::: "memory")
#define REDADD(p, v) \
    asm volatile("red.global.add.f32 [%0], %1;" :: "l"(p), "f"(v) : "memory")
__device__ __forceinline__ uint32_t sm_u32(const void* p) {
    return (uint32_t)__cvta_generic_to_shared(p);
}

// ---------------------------------------------------------------------------
// prep (vectorized, R10-proven): split x and 4 W matrices into bf16 hi/lo
// (4 floats per thread: 1x LDG.128, 2x 8B STG), and zero g_att / g_l.
// ---------------------------------------------------------------------------
#define PREP_X4  (MROWS*CC/4)              // 262144 float4 of x
#define PREP_W4  (4*128*128/4)             // 16384 float4 of W
#define PREP_Z4  (262144 + 16384)          // float4 count for g_att + g_l
#define PREP_TOT4 (PREP_X4 + PREP_W4 + PREP_Z4)   // 557056 = 2176 * 256

__global__ __launch_bounds__(256) void prep_kernel(
    const float* __restrict__ x,
    const float* __restrict__ Wk, const float* __restrict__ Wq,
    const float* __restrict__ Wv, const float* __restrict__ Wp)
{
    const int idx4 = blockIdx.x * 256 + threadIdx.x;
    if (idx4 >= PREP_X4 + PREP_W4) {
        const int z = idx4 - (PREP_X4 + PREP_W4);
        float4 zero = make_float4(0.f, 0.f, 0.f, 0.f);
        if (z < 262144) ((float4*)g_att)[z] = zero;
        else            ((float4*)g_l)[z - 262144] = zero;
        return;
    }

    float4 v;
    __nv_bfloat16* dst;  // row base; hi at [k..k+3], lo at [128+k..]
    int k;
    if (idx4 < PREP_X4) {
        const int row = idx4 >> 5;
        k = (idx4 & 31) * 4;
        v = ((const float4*)x)[idx4];
        dst = g_xb + (size_t)row * 256;
    } else {
        const int t4 = idx4 - PREP_X4;           // 0 .. 16383
        const int s = t4 >> 12, j = (t4 >> 5) & 127;
        k = (t4 & 31) * 4;
        const float* W = (s == 0) ? Wk : (s == 1) ? Wq : (s == 2) ? Wv : Wp;
        v = *(const float4*)(W + j * 128 + k);
        dst = g_wb + (size_t)(s * 128 + j) * 256;
    }

    uint32_t h0 = pack2(v.x, v.y);
    uint32_t h1 = pack2(v.z, v.w);
    uint32_t l0 = pack2(v.x - bflo(h0), v.y - bfhi(h0));
    uint32_t l1 = pack2(v.z - bflo(h1), v.w - bfhi(h1));
    *(uint2*)(dst + k)       = make_uint2(h0, h1);
    *(uint2*)(dst + 128 + k) = make_uint2(l0, l1);
}

// ---------------------------------------------------------------------------
// Tensor GEMM (64-row tiles, 256 threads = 8 warps: 4 row-groups x 2 col-
// groups; per-warp inner loop identical to the proven 32-row version).
// out[row, j] = sum_k A[row,k] * W[j,k], 3-pass bf16 hi/lo HMMA.
// sel: -1 = QKV fused (blockIdx.y: 0=Q,1=K,2=V; A cp.async from g_xb),
//      3 = output projection with FUSED normalization (A from g_att / g_l).
// Q epilogue scale = 0.25 * log2(e): scores land in log2 domain -> exp = ex2.
// ---------------------------------------------------------------------------
#define APITCH 528   // 512B data + 16 pad; (4g+q4) mod 32 -> conflict-free frags
#define QSCALE 0.36067376f   // 0.25 * 1.4426950408889634
#define TG_ROWS 64
#define TG_SMEM ((TG_ROWS + 128) * APITCH)   // 101376

__global__ __launch_bounds__(256) void tgemm_kernel(
    const float* __restrict__ bias, float* __restrict__ Oext, int selp)
{
    extern __shared__ char sm[];
    char* As = sm;                       // [64][528]
    char* Ws = sm + TG_ROWS * APITCH;    // [128][528]

    const int sel = (selp < 0) ? (int)blockIdx.y : selp;
    const int wsel = (sel == 0) ? 1 : (sel == 1) ? 0 : (sel == 2) ? 2 : 3;
    const __nv_bfloat16* Wsrc = g_wb + (size_t)wsel * 128 * 256;

    const int tid = threadIdx.x;
    const int row0 = blockIdx.x * TG_ROWS;

    // stage W (async from pre-split g_wb): 4096 x 16B
    #pragma unroll
    for (int i = tid; i < 4096; i += 256) {
        int r = i >> 5, c = i & 31;
        CP_ASYNC16(sm_u32(Ws + r * APITCH + c * 16),
                   (const char*)(Wsrc + (size_t)r * 256) + c * 16);
    }

    // stage A: 64 rows
    if (sel == 3) {
        // fused normalize + split from g_att / g_l: 2048 float4
        #pragma unroll
        for (int i = tid; i < 2048; i += 256) {
            const int r = i >> 5, c = i & 31;       // c: float4 index in row
            const int row = row0 + r;
            float4 v = *(const float4*)(g_att + (size_t)row * CC + c * 4);
            const float inv = fast_rcp(g_l[row * HH + (c >> 2)]);
            float a0 = v.x * inv, a1 = v.y * inv, a2 = v.z * inv, a3 = v.w * inv;
            uint32_t h0 = pack2(a0, a1);
            uint32_t h1 = pack2(a2, a3);
            uint32_t l0 = pack2(a0 - bflo(h0), a1 - bfhi(h0));
            uint32_t l1 = pack2(a2 - bflo(h1), a3 - bfhi(h1));
            *(uint2*)(As + r * APITCH + c * 8)       = make_uint2(h0, h1);
            *(uint2*)(As + r * APITCH + 256 + c * 8) = make_uint2(l0, l1);
        }
    } else {
        #pragma unroll
        for (int i = tid; i < 2048; i += 256) {
            int r = i >> 5, c = i & 31;
            CP_ASYNC16(sm_u32(As + r * APITCH + c * 16),
                       (const char*)(g_xb + (size_t)(row0 + r) * 256) + c * 16);
        }
    }
    CP_COMMIT(); CP_WAIT0();
    __syncthreads();

    const int wid = tid >> 5, lane = tid & 31;
    const int g = lane >> 2, q4 = lane & 3;
    const int rowg = wid >> 1, colg = wid & 1;   // rowg 0..3, colg 0..1

    float acc[8][4];
    #pragma unroll
    for (int nt = 0; nt < 8; ++nt)
        #pragma unroll
        for (int r = 0; r < 4; ++r) acc[nt][r] = 0.f;

    const char* Ab = As + (rowg * 16 + g) * APITCH;
    const char* Wb0 = Ws + (colg * 64 + g) * APITCH;

    #pragma unroll
    for (int kt = 0; kt < 8; ++kt) {
        const int ko = kt * 32 + q4 * 4;
        uint32_t ah[4], al[4];
        ah[0] = *(const uint32_t*)(Ab + ko);
        ah[1] = *(const uint32_t*)(Ab + 8 * APITCH + ko);
        ah[2] = *(const uint32_t*)(Ab + ko + 16);
        ah[3] = *(const uint32_t*)(Ab + 8 * APITCH + ko + 16);
        al[0] = *(const uint32_t*)(Ab + ko + 256);
        al[1] = *(const uint32_t*)(Ab + 8 * APITCH + ko + 256);
        al[2] = *(const uint32_t*)(Ab + ko + 272);
        al[3] = *(const uint32_t*)(Ab + 8 * APITCH + ko + 272);
        #pragma unroll
        for (int nt = 0; nt < 8; ++nt) {
            const char* wp = Wb0 + nt * 8 * APITCH + ko;
            uint32_t bh[2] = {*(const uint32_t*)(wp),       *(const uint32_t*)(wp + 16)};
            uint32_t bl[2] = {*(const uint32_t*)(wp + 256), *(const uint32_t*)(wp + 272)};
            mma16816(acc[nt], ah, bh);
            mma16816(acc[nt], al, bh);
            mma16816(acc[nt], ah, bl);
        }
    }

    const int r0 = row0 + rowg * 16 + g;
    const int b = r0 >> 12, t = r0 & (TT - 1);
    #pragma unroll
    for (int nt = 0; nt < 8; ++nt) {
        const int c = colg * 64 + nt * 8 + 2 * q4;
        if (sel == 3) {
            float2 bb = *(const float2*)(bias + c);
            *(float2*)(Oext + (size_t)r0 * 128 + c)       = make_float2(acc[nt][0] + bb.x, acc[nt][1] + bb.y);
            *(float2*)(Oext + (size_t)(r0 + 8) * 128 + c) = make_float2(acc[nt][2] + bb.x, acc[nt][3] + bb.y);
        } else {
            const int h = c >> 4, d = c & 15;
            if (sel == 2) {
                const size_t base = ((size_t)((b * HH + h) * DD + d)) * TT + t;
                __nv_bfloat16 h0 = __float2bfloat16_rn(acc[nt][0]);
                __nv_bfloat16 h1 = __float2bfloat16_rn(acc[nt][1]);
                __nv_bfloat16 h2 = __float2bfloat16_rn(acc[nt][2]);
                __nv_bfloat16 h3 = __float2bfloat16_rn(acc[nt][3]);
                g_vth[base]          = h0;
                g_vth[base + TT]     = h1;
                g_vth[base + 8]      = h2;
                g_vth[base + TT + 8] = h3;
                g_vtl[base]          = __float2bfloat16_rn(acc[nt][0] - __bfloat162float(h0));
                g_vtl[base + TT]     = __float2bfloat16_rn(acc[nt][1] - __bfloat162float(h1));
                g_vtl[base + 8]      = __float2bfloat16_rn(acc[nt][2] - __bfloat162float(h2));
                g_vtl[base + TT + 8] = __float2bfloat16_rn(acc[nt][3] - __bfloat162float(h3));
            } else {
                const size_t base = ((size_t)(b * HH + h) * TT + t) * DD + d;
                const float s = (sel == 0) ? QSCALE : 1.0f;
                __nv_bfloat16* dst = ((sel == 0) ? g_qb : g_kb) + base;
                *(uint32_t*)(dst)          = pack2(acc[nt][0] * s, acc[nt][1] * s);
                *(uint32_t*)(dst + 8 * DD) = pack2(acc[nt][2] * s, acc[nt][3] * s);
            }
        }
    }
}

// ---------------------------------------------------------------------------
// Split-K flash attention. Block = (bh, qi, split); split covers <=4 key tiles.
// exp via MUFU ex2 (log2-domain scores, scale folded into Q projection).
// Partial O and l via red.global.add.
// ---------------------------------------------------------------------------
#define KPITCH 48
#define VPLANE 4352              // 16 * 272
#define VBUF   (2*VPLANE)        // 8704

__global__ __launch_bounds__(128, 4) void attn_kernel()
{
    __shared__ __align__(16) char ksm[2][128 * KPITCH];  // 12 KB
    __shared__ __align__(16) char vsm[2][VBUF];          // 17 KB

    const int tid  = threadIdx.x;
    const int wid  = tid >> 5;
    const int lane = tid & 31;
    const int g    = lane >> 2;
    const int q4   = lane & 3;
    const int bh   = blockIdx.y;

    // ---- map blockIdx.x (0..143) -> (qi, split) ----
    const int x = blockIdx.x;
    int a = (int)((sqrtf((float)(2 * x) + 1.0f) - 1.0f) * 0.5f);
    while (2 * (a + 1) * (a + 2) <= x) ++a;
    while (2 * a * (a + 1) > x) --a;
    const int r  = x - 2 * a * (a + 1);
    const int qi    = 4 * a + r / (a + 1);
    const int split = r % (a + 1);
    const int kt0   = 4 * split;
    const int ktend = (split == a) ? (qi + 1) : (kt0 + 4);

    // ---- Q fragments (bf16, pre-scaled by 0.25*log2e) ----
    const __nv_bfloat16* Qb = g_qb + ((size_t)bh * TT + (size_t)qi * 128 + wid * 32) * DD;
    uint32_t qa[2][4];
    #pragma unroll
    for (int m = 0; m < 2; ++m) {
        const int r0 = 16 * m + g;
        qa[m][0] = *(const uint32_t*)(Qb + (size_t)r0 * DD + 2 * q4);
        qa[m][1] = *(const uint32_t*)(Qb + (size_t)(r0 + 8) * DD + 2 * q4);
        qa[m][2] = *(const uint32_t*)(Qb + (size_t)r0 * DD + 2 * q4 + 8);
        qa[m][3] = *(const uint32_t*)(Qb + (size_t)(r0 + 8) * DD + 2 * q4 + 8);
    }

    // O accumulators: [m][n 0..1 = V cols, 2 = ones column (row sums)]
    float O[2][3][4];
    #pragma unroll
    for (int m = 0; m < 2; ++m)
        #pragma unroll
        for (int n = 0; n < 3; ++n)
            #pragma unroll
            for (int rr = 0; rr < 4; ++rr) O[m][n][rr] = 0.f;

    const uint32_t vone = (g == 0) ? 0x3F803F80u : 0u;
    const uint32_t vones[2] = {vone, vone};

    const char* Kg  = (const char*)(g_kb  + ((size_t)bh * TT) * DD);
    const char* Vhg = (const char*)(g_vth + (size_t)bh * DD * TT);
    const char* Vlg = (const char*)(g_vtl + (size_t)bh * DD * TT);

    const int cid0 = tid * 4;

    // ---- stage first tile ----
    {
        uint32_t kd = sm_u32(&ksm[0][tid * KPITCH]);
        const char* ks = Kg + ((size_t)kt0 * 128 + tid) * 32;
        CP_ASYNC16(kd, ks); CP_ASYNC16(kd + 16, ks + 16);
        #pragma unroll
        for (int i = 0; i < 4; ++i) {
            const int cid = cid0 + i;
            const int pl = cid >> 8, d = (cid >> 4) & 15, ch = cid & 15;
            const char* src = (pl ? Vlg : Vhg) + ((size_t)d * TT + (size_t)kt0 * 128) * 2 + ch * 16;
            CP_ASYNC16(sm_u32(&vsm[0][pl * VPLANE + d * 272 + ch * 16]), src);
        }
        CP_COMMIT();
    }

    for (int kt = kt0; kt < ktend; ++kt) {
        const int buf = (kt - kt0) & 1;
        if (kt + 1 < ktend) {
            const int nb = buf ^ 1;
            uint32_t kd = sm_u32(&ksm[nb][tid * KPITCH]);
            const char* ks = Kg + ((size_t)(kt + 1) * 128 + tid) * 32;
            CP_ASYNC16(kd, ks); CP_ASYNC16(kd + 16, ks + 16);
            #pragma unroll
            for (int i = 0; i < 4; ++i) {
                const int cid = cid0 + i;
                const int pl = cid >> 8, d = (cid >> 4) & 15, ch = cid & 15;
                const char* src = (pl ? Vlg : Vhg) + ((size_t)d * TT + (size_t)(kt + 1) * 128) * 2 + ch * 16;
                CP_ASYNC16(sm_u32(&vsm[nb][pl * VPLANE + d * 272 + ch * 16]), src);
            }
            CP_COMMIT();
            CP_WAIT1();
        } else {
            CP_WAIT0();
        }
        __syncthreads();

        const char* kb_s = ksm[buf];
        const char* vhi  = vsm[buf];
        const char* vlo  = vsm[buf] + VPLANE;
        const bool diag = (kt == qi);
        const int nchunk = diag ? (wid + 1) : 4;

        for (int c = 0; c < nchunk; ++c) {
            const int kc = 32 * c;

            // K B-fragments
            uint32_t kb[4][2];
            #pragma unroll
            for (int nt = 0; nt < 4; ++nt) {
                const char* kp = kb_s + (kc + nt * 8 + g) * KPITCH + q4 * 4;
                kb[nt][0] = *(const uint32_t*)(kp);
                kb[nt][1] = *(const uint32_t*)(kp + 16);
            }

            // QK (single bf16 pass; scores in log2 domain)
            float S[2][4][4];
            #pragma unroll
            for (int m = 0; m < 2; ++m)
                #pragma unroll
                for (int nt = 0; nt < 4; ++nt)
                    mma16816_init(S[m][nt], qa[m], kb[nt]);

            // softmax weights: p = 2^s via MUFU (idle pipe)
            const bool dmask = diag && (c == wid);
            #pragma unroll
            for (int m = 0; m < 2; ++m) {
                const int ql0 = 32 * wid + 16 * m + g;
                #pragma unroll
                for (int nt = 0; nt < 4; ++nt) {
                    const int kl = kc + nt * 8 + 2 * q4;
                    float p0 = ex2f(S[m][nt][0]);
                    float p1 = ex2f(S[m][nt][1]);
                    float p2 = ex2f(S[m][nt][2]);
                    float p3 = ex2f(S[m][nt][3]);
                    if (dmask) {
                        if (kl     > ql0)     p0 = 0.f;
                        if (kl + 1 > ql0)     p1 = 0.f;
                        if (kl     > ql0 + 8) p2 = 0.f;
                        if (kl + 1 > ql0 + 8) p3 = 0.f;
                    }
                    S[m][nt][0] = p0; S[m][nt][1] = p1;
                    S[m][nt][2] = p2; S[m][nt][3] = p3;
                }
            }

            // pack P hi/lo A-fragments
            uint32_t ph[2][2][4], pl[2][2][4];
            #pragma unroll
            for (int m = 0; m < 2; ++m)
                #pragma unroll
                for (int s = 0; s < 2; ++s) {
                    const float* t0 = S[m][2 * s];
                    const float* t1 = S[m][2 * s + 1];
                    ph[m][s][0] = pack2(t0[0], t0[1]);
                    ph[m][s][1] = pack2(t0[2], t0[3]);
                    ph[m][s][2] = pack2(t1[0], t1[1]);
                    ph[m][s][3] = pack2(t1[2], t1[3]);
                    pl[m][s][0] = pack2(t0[0] - bflo(ph[m][s][0]), t0[1] - bfhi(ph[m][s][0]));
                    pl[m][s][1] = pack2(t0[2] - bflo(ph[m][s][1]), t0[3] - bfhi(ph[m][s][1]));
                    pl[m][s][2] = pack2(t1[0] - bflo(ph[m][s][2]), t1[1] - bfhi(ph[m][s][2]));
                    pl[m][s][3] = pack2(t1[2] - bflo(ph[m][s][3]), t1[3] - bfhi(ph[m][s][3]));
                }

            // V B-fragments: direct LDS.32 from pre-split planes
            uint32_t vh[2][2][2], vl[2][2][2];
            #pragma unroll
            for (int s = 0; s < 2; ++s)
                #pragma unroll
                for (int nt = 0; nt < 2; ++nt) {
                    const int off = (nt * 8 + g) * 272 + (kc + 16 * s + 2 * q4) * 2;
                    vh[s][nt][0] = *(const uint32_t*)(vhi + off);
                    vh[s][nt][1] = *(const uint32_t*)(vhi + off + 16);
                    vl[s][nt][0] = *(const uint32_t*)(vlo + off);
                    vl[s][nt][1] = *(const uint32_t*)(vlo + off + 16);
                }

            // PV (+ones for row sums)
            #pragma unroll
            for (int m = 0; m < 2; ++m)
                #pragma unroll
                for (int s = 0; s < 2; ++s) {
                    mma16816(O[m][0], ph[m][s], vh[s][0]);
                    mma16816(O[m][1], ph[m][s], vh[s][1]);
                    mma16816(O[m][2], ph[m][s], vones);
                    mma16816(O[m][0], pl[m][s], vh[s][0]);
                    mma16816(O[m][1], pl[m][s], vh[s][1]);
                    mma16816(O[m][2], pl[m][s], vones);
                    mma16816(O[m][0], ph[m][s], vl[s][0]);
                    mma16816(O[m][1], ph[m][s], vl[s][1]);
                }
        }
        __syncthreads();
    }

    // ---- epilogue: atomic accumulate partial O and l ----
    const int b = bh >> 3, h = bh & 7;
    #pragma unroll
    for (int m = 0; m < 2; ++m) {
        const int row0 = qi * 128 + 32 * wid + 16 * m + g;
        if (q4 == 0) {
            REDADD(&g_l[(size_t)(b * TT + row0) * HH + h],     O[m][2][0]);
            REDADD(&g_l[(size_t)(b * TT + row0 + 8) * HH + h], O[m][2][2]);
        }
        #pragma unroll
        for (int nt = 0; nt < 2; ++nt) {
            const int d = nt * 8 + 2 * q4;
            float* p0 = g_att + (size_t)(b * TT + row0) * CC + h * DD + d;
            float* p1 = g_att + (size_t)(b * TT + row0 + 8) * CC + h * DD + d;
            REDADD(p0,     O[m][nt][0]);
            REDADD(p0 + 1, O[m][nt][1]);
            REDADD(p1,     O[m][nt][2]);
            REDADD(p1 + 1, O[m][nt][3]);
        }
    }
}

// ---------------------------------------------------------------------------
// Launch: prep(+zero) -> fused QKV tgemm -> attention -> proj tgemm (fused norm)
// inputs (metadata order): x, Wk, Wq, Wv, Wp, bp
// ---------------------------------------------------------------------------
extern "C" void kernel_launch(void* const* d_in, const int* in_sizes, int n_in,
                              void* d_out, int out_size)
{
    const float* x  = (const float*)d_in[0];
    const float* Wk = (const float*)d_in[1];
    const float* Wq = (const float*)d_in[2];
    const float* Wv = (const float*)d_in[3];
    const float* Wp = (const float*)d_in[4];
    const float* bp = (const float*)d_in[5];
    float* out = (float*)d_out;

    cudaFuncSetAttribute(tgemm_kernel, cudaFuncAttributeMaxDynamicSharedMemorySize, TG_SMEM);

    prep_kernel<<<PREP_TOT4 / 256, 256>>>(x, Wk, Wq, Wv, Wp);

    dim3 qkv_grid(MROWS / TG_ROWS, 3);   // (128, 3)
    tgemm_kernel<<<qkv_grid, 256, TG_SMEM>>>(nullptr, nullptr, -1);  // Q,K,V fused

    dim3 agrid(144, NBH);
    attn_kernel<<<agrid, 128>>>();

    tgemm_kernel<<<MROWS / TG_ROWS, 256, TG_SMEM>>>(bp, out, 3);  // proj + fused norm
}

// round 16
// speedup vs baseline: 1.1167x; 1.0346x over previous
#include <cuda_runtime.h>
#include <cuda_bf16.h>
#include <cstdint>

// Problem constants
#define BB 2
#define TT 4096
#define CC 128
#define HH 8
#define DD 16
#define MROWS (BB*TT)          // 8192
#define NBH (BB*HH)            // 16

// Scratch (device globals; no allocation allowed)
__device__ __nv_bfloat16 g_xb[MROWS*256];    // [row][hi128|lo128]
__device__ __nv_bfloat16 g_wb[4*128*256];    // [sel][j][hi128|lo128] (Wk,Wq,Wv,Wp)
__device__ __nv_bfloat16 g_qb[NBH*TT*DD];    // [bh][t][16] bf16 (pre-scaled 0.25*log2e)
__device__ __nv_bfloat16 g_kb[NBH*TT*DD];    // [bh][t][16] bf16
__device__ __nv_bfloat16 g_vth[NBH*DD*TT];   // V hi, transposed: [bh*16+d][t]
__device__ __nv_bfloat16 g_vtl[NBH*DD*TT];   // V lo, transposed: [bh*16+d][t]
__device__ float g_att[MROWS*CC];            // unnormalized attn accum (atomic)
__device__ float g_l[MROWS*HH];              // row sums (atomic)

// ============================================================================
// Helpers
// ============================================================================
__device__ __forceinline__ void mma16816(float d[4], const uint32_t a[4], const uint32_t b[2]) {
    asm volatile("mma.sync.aligned.m16n8k16.row.col.f32.bf16.bf16.f32 "
        "{%0,%1,%2,%3}, {%4,%5,%6,%7}, {%8,%9}, {%0,%1,%2,%3};"
        : "+f"(d[0]), "+f"(d[1]), "+f"(d[2]), "+f"(d[3])
        : "r"(a[0]), "r"(a[1]), "r"(a[2]), "r"(a[3]), "r"(b[0]), "r"(b[1]));
}
__device__ __forceinline__ void mma16816_init(float d[4], const uint32_t a[4], const uint32_t b[2]) {
    asm volatile("mma.sync.aligned.m16n8k16.row.col.f32.bf16.bf16.f32 "
        "{%0,%1,%2,%3}, {%4,%5,%6,%7}, {%8,%9}, {%10,%10,%10,%10};"
        : "=f"(d[0]), "=f"(d[1]), "=f"(d[2]), "=f"(d[3])
        : "r"(a[0]), "r"(a[1]), "r"(a[2]), "r"(a[3]), "r"(b[0]), "r"(b[1]), "f"(0.0f));
}
__device__ __forceinline__ uint32_t pack2(float lo_el, float hi_el) {
    __nv_bfloat162 h = __floats2bfloat162_rn(lo_el, hi_el);
    return *reinterpret_cast<uint32_t*>(&h);
}
__device__ __forceinline__ float bflo(uint32_t u) { uint32_t v = u << 16;         return __uint_as_float(v); }
__device__ __forceinline__ float bfhi(uint32_t u) { uint32_t v = u & 0xFFFF0000u; return __uint_as_float(v); }
__device__ __forceinline__ float ex2f(float x) {   // p = 2^x (scale pre-folded into Q)
    float r; asm("ex2.approx.ftz.f32 %0, %1;" : "=f"(r) : "f"(x)); return r;
}
__device__ __forceinline__ float fast_rcp(float x) {
    float r; asm("rcp.approx.f32 %0, %1;" : "=f"(r) : "f"(x));
    return r * (2.0f - x * r);   // one Newton step
}
#define CP_ASYNC16(dst_u32, src_ptr) \
    asm volatile("cp.async.ca.shared.global [%0], [%1], 16;" :: "r"(dst_u32), "l"(src_ptr))
#define CP_COMMIT() asm volatile("cp.async.commit_group;" ::: "memory")
#define CP_WAIT0()  asm volatile("cp.async.wait_group 0;" ::: "memory")
#define CP_WAIT1()  asm volatile("cp.async.wait_group 1;" ::: "memory")
#define REDADD(p, v) \
    asm volatile("red.global.add.f32 [%0], %1;" :: "l"(p), "f"(v) : "memory")
__device__ __forceinline__ uint32_t sm_u32(const void* p) {
    return (uint32_t)__cvta_generic_to_shared(p);
}

// ---------------------------------------------------------------------------
// prep (vectorized, R10-proven): split x and 4 W matrices into bf16 hi/lo
// (4 floats per thread: 1x LDG.128, 2x 8B STG), and zero g_att / g_l.
// ---------------------------------------------------------------------------
#define PREP_X4  (MROWS*CC/4)              // 262144 float4 of x
#define PREP_W4  (4*128*128/4)             // 16384 float4 of W
#define PREP_Z4  (262144 + 16384)          // float4 count for g_att + g_l
#define PREP_TOT4 (PREP_X4 + PREP_W4 + PREP_Z4)   // 557056 = 2176 * 256

__global__ __launch_bounds__(256) void prep_kernel(
    const float* __restrict__ x,
    const float* __restrict__ Wk, const float* __restrict__ Wq,
    const float* __restrict__ Wv, const float* __restrict__ Wp)
{
    const int idx4 = blockIdx.x * 256 + threadIdx.x;
    if (idx4 >= PREP_X4 + PREP_W4) {
        const int z = idx4 - (PREP_X4 + PREP_W4);
        float4 zero = make_float4(0.f, 0.f, 0.f, 0.f);
        if (z < 262144) ((float4*)g_att)[z] = zero;
        else            ((float4*)g_l)[z - 262144] = zero;
        return;
    }

    float4 v;
    __nv_bfloat16* dst;  // row base; hi at [k..k+3], lo at [128+k..]
    int k;
    if (idx4 < PREP_X4) {
        const int row = idx4 >> 5;
        k = (idx4 & 31) * 4;
        v = ((const float4*)x)[idx4];
        dst = g_xb + (size_t)row * 256;
    } else {
        const int t4 = idx4 - PREP_X4;           // 0 .. 16383
        const int s = t4 >> 12, j = (t4 >> 5) & 127;
        k = (t4 & 31) * 4;
        const float* W = (s == 0) ? Wk : (s == 1) ? Wq : (s == 2) ? Wv : Wp;
        v = *(const float4*)(W + j * 128 + k);
        dst = g_wb + (size_t)(s * 128 + j) * 256;
    }

    uint32_t h0 = pack2(v.x, v.y);
    uint32_t h1 = pack2(v.z, v.w);
    uint32_t l0 = pack2(v.x - bflo(h0), v.y - bfhi(h0));
    uint32_t l1 = pack2(v.z - bflo(h1), v.w - bfhi(h1));
    *(uint2*)(dst + k)       = make_uint2(h0, h1);
    *(uint2*)(dst + 128 + k) = make_uint2(l0, l1);
}

// ---------------------------------------------------------------------------
// Tensor GEMM (64-row tiles, 256 threads = 8 warps: 4 row-groups x 2 col-
// groups). Staging PIPELINED in two k-halves: kt 0..3 uses byte-chunks
// {0..7,16..23}, kt 4..7 uses {8..15,24..31}; compute of half 0 overlaps the
// async staging of half 1.
// sel: -1 = QKV fused (blockIdx.y: 0=Q,1=K,2=V; A cp.async from g_xb),
//      3 = output projection with FUSED normalization (A from g_att / g_l,
//          computed in the shadow of the W cp.async).
// ---------------------------------------------------------------------------
#define APITCH 528   // 512B data + 16 pad; (4g+q4) mod 32 -> conflict-free frags
#define QSCALE 0.36067376f   // 0.25 * 1.4426950408889634
#define TG_ROWS 64
#define TG_SMEM ((TG_ROWS + 128) * APITCH)   // 101376

__global__ __launch_bounds__(256) void tgemm_kernel(
    const float* __restrict__ bias, float* __restrict__ Oext, int selp)
{
    extern __shared__ char sm[];
    char* As = sm;                       // [64][528]
    char* Ws = sm + TG_ROWS * APITCH;    // [128][528]

    const int sel = (selp < 0) ? (int)blockIdx.y : selp;
    const int wsel = (sel == 0) ? 1 : (sel == 1) ? 0 : (sel == 2) ? 2 : 3;
    const __nv_bfloat16* Wsrc = g_wb + (size_t)wsel * 128 * 256;

    const int tid = threadIdx.x;
    const int row0 = blockIdx.x * TG_ROWS;

    // ---- stage in two k-halves (chunk c = (cc&7) + ((cc>>3)<<4) + 8*hf) ----
    #pragma unroll
    for (int hf = 0; hf < 2; ++hf) {
        if (sel != 3) {
            #pragma unroll
            for (int i = tid; i < 1024; i += 256) {       // A: 64 rows x 16 chunks
                int r = i >> 4, cc = i & 15;
                int c = (cc & 7) + ((cc >> 3) << 4) + 8 * hf;
                CP_ASYNC16(sm_u32(As + r * APITCH + c * 16),
                           (const char*)(g_xb + (size_t)(row0 + r) * 256) + c * 16);
            }
        }
        #pragma unroll
        for (int i = tid; i < 2048; i += 256) {           // W: 128 rows x 16 chunks
            int r = i >> 4, cc = i & 15;
            int c = (cc & 7) + ((cc >> 3) << 4) + 8 * hf;
            CP_ASYNC16(sm_u32(Ws + r * APITCH + c * 16),
                       (const char*)(Wsrc + (size_t)r * 256) + c * 16);
        }
        CP_COMMIT();
    }

    if (sel == 3) {
        // fused normalize + split from g_att / g_l (runs under W cp.async)
        #pragma unroll
        for (int i = tid; i < 2048; i += 256) {
            const int r = i >> 5, c = i & 31;       // c: float4 index in row
            const int row = row0 + r;
            float4 v = *(const float4*)(g_att + (size_t)row * CC + c * 4);
            const float inv = fast_rcp(g_l[row * HH + (c >> 2)]);
            float a0 = v.x * inv, a1 = v.y * inv, a2 = v.z * inv, a3 = v.w * inv;
            uint32_t h0 = pack2(a0, a1);
            uint32_t h1 = pack2(a2, a3);
            uint32_t l0 = pack2(a0 - bflo(h0), a1 - bfhi(h0));
            uint32_t l1 = pack2(a2 - bflo(h1), a3 - bfhi(h1));
            *(uint2*)(As + r * APITCH + c * 8)       = make_uint2(h0, h1);
            *(uint2*)(As + r * APITCH + 256 + c * 8) = make_uint2(l0, l1);
        }
    }

    const int wid = tid >> 5, lane = tid & 31;
    const int g = lane >> 2, q4 = lane & 3;
    const int rowg = wid >> 1, colg = wid & 1;   // rowg 0..3, colg 0..1

    float acc[8][4];
    #pragma unroll
    for (int nt = 0; nt < 8; ++nt)
        #pragma unroll
        for (int r = 0; r < 4; ++r) acc[nt][r] = 0.f;

    const char* Ab = As + (rowg * 16 + g) * APITCH;
    const char* Wb0 = Ws + (colg * 64 + g) * APITCH;

    #pragma unroll
    for (int half = 0; half < 2; ++half) {
        if (half == 0) { CP_WAIT1(); } else { CP_WAIT0(); }
        __syncthreads();
        #pragma unroll
        for (int kt = half * 4; kt < half * 4 + 4; ++kt) {
            const int ko = kt * 32 + q4 * 4;
            uint32_t ah[4], al[4];
            ah[0] = *(const uint32_t*)(Ab + ko);
            ah[1] = *(const uint32_t*)(Ab + 8 * APITCH + ko);
            ah[2] = *(const uint32_t*)(Ab + ko + 16);
            ah[3] = *(const uint32_t*)(Ab + 8 * APITCH + ko + 16);
            al[0] = *(const uint32_t*)(Ab + ko + 256);
            al[1] = *(const uint32_t*)(Ab + 8 * APITCH + ko + 256);
            al[2] = *(const uint32_t*)(Ab + ko + 272);
            al[3] = *(const uint32_t*)(Ab + 8 * APITCH + ko + 272);
            #pragma unroll
            for (int nt = 0; nt < 8; ++nt) {
                const char* wp = Wb0 + nt * 8 * APITCH + ko;
                uint32_t bh[2] = {*(const uint32_t*)(wp),       *(const uint32_t*)(wp + 16)};
                uint32_t bl[2] = {*(const uint32_t*)(wp + 256), *(const uint32_t*)(wp + 272)};
                mma16816(acc[nt], ah, bh);
                mma16816(acc[nt], al, bh);
                mma16816(acc[nt], ah, bl);
            }
        }
    }

    const int r0 = row0 + rowg * 16 + g;
    const int b = r0 >> 12, t = r0 & (TT - 1);
    #pragma unroll
    for (int nt = 0; nt < 8; ++nt) {
        const int c = colg * 64 + nt * 8 + 2 * q4;
        if (sel == 3) {
            float2 bb = *(const float2*)(bias + c);
            *(float2*)(Oext + (size_t)r0 * 128 + c)       = make_float2(acc[nt][0] + bb.x, acc[nt][1] + bb.y);
            *(float2*)(Oext + (size_t)(r0 + 8) * 128 + c) = make_float2(acc[nt][2] + bb.x, acc[nt][3] + bb.y);
        } else {
            const int h = c >> 4, d = c & 15;
            if (sel == 2) {
                const size_t base = ((size_t)((b * HH + h) * DD + d)) * TT + t;
                __nv_bfloat16 h0 = __float2bfloat16_rn(acc[nt][0]);
                __nv_bfloat16 h1 = __float2bfloat16_rn(acc[nt][1]);
                __nv_bfloat16 h2 = __float2bfloat16_rn(acc[nt][2]);
                __nv_bfloat16 h3 = __float2bfloat16_rn(acc[nt][3]);
                g_vth[base]          = h0;
                g_vth[base + TT]     = h1;
                g_vth[base + 8]      = h2;
                g_vth[base + TT + 8] = h3;
                g_vtl[base]          = __float2bfloat16_rn(acc[nt][0] - __bfloat162float(h0));
                g_vtl[base + TT]     = __float2bfloat16_rn(acc[nt][1] - __bfloat162float(h1));
                g_vtl[base + 8]      = __float2bfloat16_rn(acc[nt][2] - __bfloat162float(h2));
                g_vtl[base + TT + 8] = __float2bfloat16_rn(acc[nt][3] - __bfloat162float(h3));
            } else {
                const size_t base = ((size_t)(b * HH + h) * TT + t) * DD + d;
                const float s = (sel == 0) ? QSCALE : 1.0f;
                __nv_bfloat16* dst = ((sel == 0) ? g_qb : g_kb) + base;
                *(uint32_t*)(dst)          = pack2(acc[nt][0] * s, acc[nt][1] * s);
                *(uint32_t*)(dst + 8 * DD) = pack2(acc[nt][2] * s, acc[nt][3] * s);
            }
        }
    }
}

// ---------------------------------------------------------------------------
// Split-K flash attention. Block = (bh, qi, split); split covers <=4 key tiles.
// exp via MUFU ex2 (log2-domain scores). Row sums from ph-only ones column
// (pl contribution to l dropped: E[p-ph]=0 -> per-row bias ~1e-4).
// Partial O and l via red.global.add.
// ---------------------------------------------------------------------------
#define KPITCH 48
#define VPLANE 4352              // 16 * 272
#define VBUF   (2*VPLANE)        // 8704

__global__ __launch_bounds__(128, 4) void attn_kernel()
{
    __shared__ __align__(16) char ksm[2][128 * KPITCH];  // 12 KB
    __shared__ __align__(16) char vsm[2][VBUF];          // 17 KB

    const int tid  = threadIdx.x;
    const int wid  = tid >> 5;
    const int lane = tid & 31;
    const int g    = lane >> 2;
    const int q4   = lane & 3;
    const int bh   = blockIdx.y;

    // ---- map blockIdx.x (0..143) -> (qi, split) ----
    const int x = blockIdx.x;
    int a = (int)((sqrtf((float)(2 * x) + 1.0f) - 1.0f) * 0.5f);
    while (2 * (a + 1) * (a + 2) <= x) ++a;
    while (2 * a * (a + 1) > x) --a;
    const int r  = x - 2 * a * (a + 1);
    const int qi    = 4 * a + r / (a + 1);
    const int split = r % (a + 1);
    const int kt0   = 4 * split;
    const int ktend = (split == a) ? (qi + 1) : (kt0 + 4);

    // ---- Q fragments (bf16, pre-scaled by 0.25*log2e) ----
    const __nv_bfloat16* Qb = g_qb + ((size_t)bh * TT + (size_t)qi * 128 + wid * 32) * DD;
    uint32_t qa[2][4];
    #pragma unroll
    for (int m = 0; m < 2; ++m) {
        const int r0 = 16 * m + g;
        qa[m][0] = *(const uint32_t*)(Qb + (size_t)r0 * DD + 2 * q4);
        qa[m][1] = *(const uint32_t*)(Qb + (size_t)(r0 + 8) * DD + 2 * q4);
        qa[m][2] = *(const uint32_t*)(Qb + (size_t)r0 * DD + 2 * q4 + 8);
        qa[m][3] = *(const uint32_t*)(Qb + (size_t)(r0 + 8) * DD + 2 * q4 + 8);
    }

    // O accumulators: [m][n 0..1 = V cols, 2 = ones column (row sums)]
    float O[2][3][4];
    #pragma unroll
    for (int m = 0; m < 2; ++m)
        #pragma unroll
        for (int n = 0; n < 3; ++n)
            #pragma unroll
            for (int rr = 0; rr < 4; ++rr) O[m][n][rr] = 0.f;

    const uint32_t vone = (g == 0) ? 0x3F803F80u : 0u;
    const uint32_t vones[2] = {vone, vone};

    const char* Kg  = (const char*)(g_kb  + ((size_t)bh * TT) * DD);
    const char* Vhg = (const char*)(g_vth + (size_t)bh * DD * TT);
    const char* Vlg = (const char*)(g_vtl + (size_t)bh * DD * TT);

    const int cid0 = tid * 4;

    // ---- stage first tile ----
    {
        uint32_t kd = sm_u32(&ksm[0][tid * KPITCH]);
        const char* ks = Kg + ((size_t)kt0 * 128 + tid) * 32;
        CP_ASYNC16(kd, ks); CP_ASYNC16(kd + 16, ks + 16);
        #pragma unroll
        for (int i = 0; i < 4; ++i) {
            const int cid = cid0 + i;
            const int pl = cid >> 8, d = (cid >> 4) & 15, ch = cid & 15;
            const char* src = (pl ? Vlg : Vhg) + ((size_t)d * TT + (size_t)kt0 * 128) * 2 + ch * 16;
            CP_ASYNC16(sm_u32(&vsm[0][pl * VPLANE + d * 272 + ch * 16]), src);
        }
        CP_COMMIT();
    }

    for (int kt = kt0; kt < ktend; ++kt) {
        const int buf = (kt - kt0) & 1;
        if (kt + 1 < ktend) {
            const int nb = buf ^ 1;
            uint32_t kd = sm_u32(&ksm[nb][tid * KPITCH]);
            const char* ks = Kg + ((size_t)(kt + 1) * 128 + tid) * 32;
            CP_ASYNC16(kd, ks); CP_ASYNC16(kd + 16, ks + 16);
            #pragma unroll
            for (int i = 0; i < 4; ++i) {
                const int cid = cid0 + i;
                const int pl = cid >> 8, d = (cid >> 4) & 15, ch = cid & 15;
                const char* src = (pl ? Vlg : Vhg) + ((size_t)d * TT + (size_t)(kt + 1) * 128) * 2 + ch * 16;
                CP_ASYNC16(sm_u32(&vsm[nb][pl * VPLANE + d * 272 + ch * 16]), src);
            }
            CP_COMMIT();
            CP_WAIT1();
        } else {
            CP_WAIT0();
        }
        __syncthreads();

        const char* kb_s = ksm[buf];
        const char* vhi  = vsm[buf];
        const char* vlo  = vsm[buf] + VPLANE;
        const bool diag = (kt == qi);
        const int nchunk = diag ? (wid + 1) : 4;

        for (int c = 0; c < nchunk; ++c) {
            const int kc = 32 * c;

            // K B-fragments
            uint32_t kb[4][2];
            #pragma unroll
            for (int nt = 0; nt < 4; ++nt) {
                const char* kp = kb_s + (kc + nt * 8 + g) * KPITCH + q4 * 4;
                kb[nt][0] = *(const uint32_t*)(kp);
                kb[nt][1] = *(const uint32_t*)(kp + 16);
            }

            // QK (single bf16 pass; scores in log2 domain)
            float S[2][4][4];
            #pragma unroll
            for (int m = 0; m < 2; ++m)
                #pragma unroll
                for (int nt = 0; nt < 4; ++nt)
                    mma16816_init(S[m][nt], qa[m], kb[nt]);

            // softmax weights: p = 2^s via MUFU (idle pipe)
            const bool dmask = diag && (c == wid);
            #pragma unroll
            for (int m = 0; m < 2; ++m) {
                const int ql0 = 32 * wid + 16 * m + g;
                #pragma unroll
                for (int nt = 0; nt < 4; ++nt) {
                    const int kl = kc + nt * 8 + 2 * q4;
                    float p0 = ex2f(S[m][nt][0]);
                    float p1 = ex2f(S[m][nt][1]);
                    float p2 = ex2f(S[m][nt][2]);
                    float p3 = ex2f(S[m][nt][3]);
                    if (dmask) {
                        if (kl     > ql0)     p0 = 0.f;
                        if (kl + 1 > ql0)     p1 = 0.f;
                        if (kl     > ql0 + 8) p2 = 0.f;
                        if (kl + 1 > ql0 + 8) p3 = 0.f;
                    }
                    S[m][nt][0] = p0; S[m][nt][1] = p1;
                    S[m][nt][2] = p2; S[m][nt][3] = p3;
                }
            }

            // pack P hi/lo A-fragments
            uint32_t ph[2][2][4], pl[2][2][4];
            #pragma unroll
            for (int m = 0; m < 2; ++m)
                #pragma unroll
                for (int s = 0; s < 2; ++s) {
                    const float* t0 = S[m][2 * s];
                    const float* t1 = S[m][2 * s + 1];
                    ph[m][s][0] = pack2(t0[0], t0[1]);
                    ph[m][s][1] = pack2(t0[2], t0[3]);
                    ph[m][s][2] = pack2(t1[0], t1[1]);
                    ph[m][s][3] = pack2(t1[2], t1[3]);
                    pl[m][s][0] = pack2(t0[0] - bflo(ph[m][s][0]), t0[1] - bfhi(ph[m][s][0]));
                    pl[m][s][1] = pack2(t0[2] - bflo(ph[m][s][1]), t0[3] - bfhi(ph[m][s][1]));
                    pl[m][s][2] = pack2(t1[0] - bflo(ph[m][s][2]), t1[1] - bfhi(ph[m][s][2]));
                    pl[m][s][3] = pack2(t1[2] - bflo(ph[m][s][3]), t1[3] - bfhi(ph[m][s][3]));
                }

            // V B-fragments: direct LDS.32 from pre-split planes
            uint32_t vh[2][2][2], vl[2][2][2];
            #pragma unroll
            for (int s = 0; s < 2; ++s)
                #pragma unroll
                for (int nt = 0; nt < 2; ++nt) {
                    const int off = (nt * 8 + g) * 272 + (kc + 16 * s + 2 * q4) * 2;
                    vh[s][nt][0] = *(const uint32_t*)(vhi + off);
                    vh[s][nt][1] = *(const uint32_t*)(vhi + off + 16);
                    vl[s][nt][0] = *(const uint32_t*)(vlo + off);
                    vl[s][nt][1] = *(const uint32_t*)(vlo + off + 16);
                }

            // PV (+ones for row sums; ph-only l)
            #pragma unroll
            for (int m = 0; m < 2; ++m)
                #pragma unroll
                for (int s = 0; s < 2; ++s) {
                    mma16816(O[m][0], ph[m][s], vh[s][0]);
                    mma16816(O[m][1], ph[m][s], vh[s][1]);
                    mma16816(O[m][2], ph[m][s], vones);
                    mma16816(O[m][0], pl[m][s], vh[s][0]);
                    mma16816(O[m][1], pl[m][s], vh[s][1]);
                    mma16816(O[m][0], ph[m][s], vl[s][0]);
                    mma16816(O[m][1], ph[m][s], vl[s][1]);
                }
        }
        __syncthreads();
    }

    // ---- epilogue: atomic accumulate partial O and l ----
    const int b = bh >> 3, h = bh & 7;
    #pragma unroll
    for (int m = 0; m < 2; ++m) {
        const int row0 = qi * 128 + 32 * wid + 16 * m + g;
        if (q4 == 0) {
            REDADD(&g_l[(size_t)(b * TT + row0) * HH + h],     O[m][2][0]);
            REDADD(&g_l[(size_t)(b * TT + row0 + 8) * HH + h], O[m][2][2]);
        }
        #pragma unroll
        for (int nt = 0; nt < 2; ++nt) {
            const int d = nt * 8 + 2 * q4;
            float* p0 = g_att + (size_t)(b * TT + row0) * CC + h * DD + d;
            float* p1 = g_att + (size_t)(b * TT + row0 + 8) * CC + h * DD + d;
            REDADD(p0,     O[m][nt][0]);
            REDADD(p0 + 1, O[m][nt][1]);
            REDADD(p1,     O[m][nt][2]);
            REDADD(p1 + 1, O[m][nt][3]);
        }
    }
}

// ---------------------------------------------------------------------------
// Launch: prep(+zero) -> fused QKV tgemm -> attention -> proj tgemm (fused norm)
// inputs (metadata order): x, Wk, Wq, Wv, Wp, bp
// ---------------------------------------------------------------------------
extern "C" void kernel_launch(void* const* d_in, const int* in_sizes, int n_in,
                              void* d_out, int out_size)
{
    const float* x  = (const float*)d_in[0];
    const float* Wk = (const float*)d_in[1];
    const float* Wq = (const float*)d_in[2];
    const float* Wv = (const float*)d_in[3];
    const float* Wp = (const float*)d_in[4];
    const float* bp = (const float*)d_in[5];
    float* out = (float*)d_out;

    cudaFuncSetAttribute(tgemm_kernel, cudaFuncAttributeMaxDynamicSharedMemorySize, TG_SMEM);

    prep_kernel<<<PREP_TOT4 / 256, 256>>>(x, Wk, Wq, Wv, Wp);

    dim3 qkv_grid(MROWS / TG_ROWS, 3);   // (128, 3)
    tgemm_kernel<<<qkv_grid, 256, TG_SMEM>>>(nullptr, nullptr, -1);  // Q,K,V fused

    dim3 agrid(144, NBH);
    attn_kernel<<<agrid, 128>>>();

    tgemm_kernel<<<MROWS / TG_ROWS, 256, TG_SMEM>>>(bp, out, 3);  // proj + fused norm
}

// round 17
// speedup vs baseline: 1.1649x; 1.0432x over previous
#include <cuda_runtime.h>
#include <cuda_bf16.h>
#include <cstdint>

// Problem constants
#define BB 2
#define TT 4096
#define CC 128
#define HH 8
#define DD 16
#define MROWS (BB*TT)          // 8192
#define NBH (BB*HH)            // 16

// Scratch (device globals; no allocation allowed)
__device__ __nv_bfloat16 g_xb[MROWS*256];    // [row][hi128|lo128]
__device__ __nv_bfloat16 g_wb[4*128*256];    // [sel][j][hi128|lo128] (Wk,Wq,Wv,Wp)
__device__ __nv_bfloat16 g_qb[NBH*TT*DD];    // [bh][t][16] bf16 (pre-scaled 0.25*log2e)
__device__ __nv_bfloat16 g_kb[NBH*TT*DD];    // [bh][t][16] bf16
__device__ __nv_bfloat16 g_vth[NBH*DD*TT];   // V hi, transposed: [bh*16+d][t]
__device__ __nv_bfloat16 g_vtl[NBH*DD*TT];   // V lo, transposed: [bh*16+d][t]
__device__ float g_att[MROWS*CC];            // unnormalized attn accum (atomic)
__device__ float g_l[MROWS*HH];              // row sums (atomic)

// ============================================================================
// Helpers
// ============================================================================
__device__ __forceinline__ void mma16816(float d[4], const uint32_t a[4], const uint32_t b[2]) {
    asm volatile("mma.sync.aligned.m16n8k16.row.col.f32.bf16.bf16.f32 "
        "{%0,%1,%2,%3}, {%4,%5,%6,%7}, {%8,%9}, {%0,%1,%2,%3};"
        : "+f"(d[0]), "+f"(d[1]), "+f"(d[2]), "+f"(d[3])
        : "r"(a[0]), "r"(a[1]), "r"(a[2]), "r"(a[3]), "r"(b[0]), "r"(b[1]));
}
__device__ __forceinline__ void mma16816_init(float d[4], const uint32_t a[4], const uint32_t b[2]) {
    asm volatile("mma.sync.aligned.m16n8k16.row.col.f32.bf16.bf16.f32 "
        "{%0,%1,%2,%3}, {%4,%5,%6,%7}, {%8,%9}, {%10,%10,%10,%10};"
        : "=f"(d[0]), "=f"(d[1]), "=f"(d[2]), "=f"(d[3])
        : "r"(a[0]), "r"(a[1]), "r"(a[2]), "r"(a[3]), "r"(b[0]), "r"(b[1]), "f"(0.0f));
}
#define LDSM_X4(r0, r1, r2, r3, addr) \
    asm volatile("ldmatrix.sync.aligned.m8n8.x4.shared.b16 {%0,%1,%2,%3}, [%4];" \
        : "=r"(r0), "=r"(r1), "=r"(r2), "=r"(r3) : "r"(addr))
__device__ __forceinline__ uint32_t pack2(float lo_el, float hi_el) {
    __nv_bfloat162 h = __floats2bfloat162_rn(lo_el, hi_el);
    return *reinterpret_cast<uint32_t*>(&h);
}
__device__ __forceinline__ float bflo(uint32_t u) { uint32_t v = u << 16;         return __uint_as_float(v); }
__device__ __forceinline__ float bfhi(uint32_t u) { uint32_t v = u & 0xFFFF0000u; return __uint_as_float(v); }
__device__ __forceinline__ float ex2f(float x) {   // p = 2^x (scale pre-folded into Q)
    float r; asm("ex2.approx.ftz.f32 %0, %1;" : "=f"(r) : "f"(x)); return r;
}
__device__ __forceinline__ float fast_rcp(float x) {
    float r; asm("rcp.approx.f32 %0, %1;" : "=f"(r) : "f"(x));
    return r * (2.0f - x * r);   // one Newton step
}
#define CP_ASYNC16(dst_u32, src_ptr) \
    asm volatile("cp.async.ca.shared.global [%0], [%1], 16;" :: "r"(dst_u32), "l"(src_ptr))
#define CP_COMMIT() asm volatile("cp.async.commit_group;" ::: "memory")
#define CP_WAIT0()  asm volatile("cp.async.wait_group 0;" ::: "memory")
#define CP_WAIT1()  asm volatile("cp.async.wait_group 1;" ::: "memory")
#define REDADD(p, v) \
    asm volatile("red.global.add.f32 [%0], %1;" :: "l"(p), "f"(v) : "memory")
__device__ __forceinline__ uint32_t sm_u32(const void* p) {
    return (uint32_t)__cvta_generic_to_shared(p);
}

// ---------------------------------------------------------------------------
// prep (vectorized, R10-proven): split x and 4 W matrices into bf16 hi/lo
// (4 floats per thread: 1x LDG.128, 2x 8B STG), and zero g_att / g_l.
// ---------------------------------------------------------------------------
#define PREP_X4  (MROWS*CC/4)              // 262144 float4 of x
#define PREP_W4  (4*128*128/4)             // 16384 float4 of W
#define PREP_Z4  (262144 + 16384)          // float4 count for g_att + g_l
#define PREP_TOT4 (PREP_X4 + PREP_W4 + PREP_Z4)   // 557056 = 2176 * 256

__global__ __launch_bounds__(256) void prep_kernel(
    const float* __restrict__ x,
    const float* __restrict__ Wk, const float* __restrict__ Wq,
    const float* __restrict__ Wv, const float* __restrict__ Wp)
{
    const int idx4 = blockIdx.x * 256 + threadIdx.x;
    if (idx4 >= PREP_X4 + PREP_W4) {
        const int z = idx4 - (PREP_X4 + PREP_W4);
        float4 zero = make_float4(0.f, 0.f, 0.f, 0.f);
        if (z < 262144) ((float4*)g_att)[z] = zero;
        else            ((float4*)g_l)[z - 262144] = zero;
        return;
    }

    float4 v;
    __nv_bfloat16* dst;  // row base; hi at [k..k+3], lo at [128+k..]
    int k;
    if (idx4 < PREP_X4) {
        const int row = idx4 >> 5;
        k = (idx4 & 31) * 4;
        v = ((const float4*)x)[idx4];
        dst = g_xb + (size_t)row * 256;
    } else {
        const int t4 = idx4 - PREP_X4;           // 0 .. 16383
        const int s = t4 >> 12, j = (t4 >> 5) & 127;
        k = (t4 & 31) * 4;
        const float* W = (s == 0) ? Wk : (s == 1) ? Wq : (s == 2) ? Wv : Wp;
        v = *(const float4*)(W + j * 128 + k);
        dst = g_wb + (size_t)(s * 128 + j) * 256;
    }

    uint32_t h0 = pack2(v.x, v.y);
    uint32_t h1 = pack2(v.z, v.w);
    uint32_t l0 = pack2(v.x - bflo(h0), v.y - bfhi(h0));
    uint32_t l1 = pack2(v.z - bflo(h1), v.w - bfhi(h1));
    *(uint2*)(dst + k)       = make_uint2(h0, h1);
    *(uint2*)(dst + 128 + k) = make_uint2(l0, l1);
}

// ---------------------------------------------------------------------------
// Tensor GEMM (64-row tiles, 256 threads = 8 warps). Staging pipelined in
// two k-halves (kt 0..3: chunks {0..7,16..23}; kt 4..7: {8..15,24..31}).
// sel: -1 = QKV fused (blockIdx.y), 3 = proj with fused normalization.
// ---------------------------------------------------------------------------
#define APITCH 528   // 512B data + 16 pad; (4g+q4) mod 32 -> conflict-free frags
#define QSCALE 0.36067376f   // 0.25 * 1.4426950408889634
#define TG_ROWS 64
#define TG_SMEM ((TG_ROWS + 128) * APITCH)   // 101376

__global__ __launch_bounds__(256) void tgemm_kernel(
    const float* __restrict__ bias, float* __restrict__ Oext, int selp)
{
    extern __shared__ char sm[];
    char* As = sm;                       // [64][528]
    char* Ws = sm + TG_ROWS * APITCH;    // [128][528]

    const int sel = (selp < 0) ? (int)blockIdx.y : selp;
    const int wsel = (sel == 0) ? 1 : (sel == 1) ? 0 : (sel == 2) ? 2 : 3;
    const __nv_bfloat16* Wsrc = g_wb + (size_t)wsel * 128 * 256;

    const int tid = threadIdx.x;
    const int row0 = blockIdx.x * TG_ROWS;

    // ---- stage in two k-halves (chunk c = (cc&7) + ((cc>>3)<<4) + 8*hf) ----
    #pragma unroll
    for (int hf = 0; hf < 2; ++hf) {
        if (sel != 3) {
            #pragma unroll
            for (int i = tid; i < 1024; i += 256) {       // A: 64 rows x 16 chunks
                int r = i >> 4, cc = i & 15;
                int c = (cc & 7) + ((cc >> 3) << 4) + 8 * hf;
                CP_ASYNC16(sm_u32(As + r * APITCH + c * 16),
                           (const char*)(g_xb + (size_t)(row0 + r) * 256) + c * 16);
            }
        }
        #pragma unroll
        for (int i = tid; i < 2048; i += 256) {           // W: 128 rows x 16 chunks
            int r = i >> 4, cc = i & 15;
            int c = (cc & 7) + ((cc >> 3) << 4) + 8 * hf;
            CP_ASYNC16(sm_u32(Ws + r * APITCH + c * 16),
                       (const char*)(Wsrc + (size_t)r * 256) + c * 16);
        }
        CP_COMMIT();
    }

    if (sel == 3) {
        // fused normalize + split from g_att / g_l (runs under W cp.async)
        #pragma unroll
        for (int i = tid; i < 2048; i += 256) {
            const int r = i >> 5, c = i & 31;       // c: float4 index in row
            const int row = row0 + r;
            float4 v = *(const float4*)(g_att + (size_t)row * CC + c * 4);
            const float inv = fast_rcp(g_l[row * HH + (c >> 2)]);
            float a0 = v.x * inv, a1 = v.y * inv, a2 = v.z * inv, a3 = v.w * inv;
            uint32_t h0 = pack2(a0, a1);
            uint32_t h1 = pack2(a2, a3);
            uint32_t l0 = pack2(a0 - bflo(h0), a1 - bfhi(h0));
            uint32_t l1 = pack2(a2 - bflo(h1), a3 - bfhi(h1));
            *(uint2*)(As + r * APITCH + c * 8)       = make_uint2(h0, h1);
            *(uint2*)(As + r * APITCH + 256 + c * 8) = make_uint2(l0, l1);
        }
    }

    const int wid = tid >> 5, lane = tid & 31;
    const int g = lane >> 2, q4 = lane & 3;
    const int rowg = wid >> 1, colg = wid & 1;   // rowg 0..3, colg 0..1

    float acc[8][4];
    #pragma unroll
    for (int nt = 0; nt < 8; ++nt)
        #pragma unroll
        for (int r = 0; r < 4; ++r) acc[nt][r] = 0.f;

    const char* Ab = As + (rowg * 16 + g) * APITCH;
    const char* Wb0 = Ws + (colg * 64 + g) * APITCH;

    #pragma unroll
    for (int half = 0; half < 2; ++half) {
        if (half == 0) { CP_WAIT1(); } else { CP_WAIT0(); }
        __syncthreads();
        #pragma unroll
        for (int kt = half * 4; kt < half * 4 + 4; ++kt) {
            const int ko = kt * 32 + q4 * 4;
            uint32_t ah[4], al[4];
            ah[0] = *(const uint32_t*)(Ab + ko);
            ah[1] = *(const uint32_t*)(Ab + 8 * APITCH + ko);
            ah[2] = *(const uint32_t*)(Ab + ko + 16);
            ah[3] = *(const uint32_t*)(Ab + 8 * APITCH + ko + 16);
            al[0] = *(const uint32_t*)(Ab + ko + 256);
            al[1] = *(const uint32_t*)(Ab + 8 * APITCH + ko + 256);
            al[2] = *(const uint32_t*)(Ab + ko + 272);
            al[3] = *(const uint32_t*)(Ab + 8 * APITCH + ko + 272);
            #pragma unroll
            for (int nt = 0; nt < 8; ++nt) {
                const char* wp = Wb0 + nt * 8 * APITCH + ko;
                uint32_t bh[2] = {*(const uint32_t*)(wp),       *(const uint32_t*)(wp + 16)};
                uint32_t bl[2] = {*(const uint32_t*)(wp + 256), *(const uint32_t*)(wp + 272)};
                mma16816(acc[nt], ah, bh);
                mma16816(acc[nt], al, bh);
                mma16816(acc[nt], ah, bl);
            }
        }
    }

    const int r0 = row0 + rowg * 16 + g;
    const int b = r0 >> 12, t = r0 & (TT - 1);
    #pragma unroll
    for (int nt = 0; nt < 8; ++nt) {
        const int c = colg * 64 + nt * 8 + 2 * q4;
        if (sel == 3) {
            float2 bb = *(const float2*)(bias + c);
            *(float2*)(Oext + (size_t)r0 * 128 + c)       = make_float2(acc[nt][0] + bb.x, acc[nt][1] + bb.y);
            *(float2*)(Oext + (size_t)(r0 + 8) * 128 + c) = make_float2(acc[nt][2] + bb.x, acc[nt][3] + bb.y);
        } else {
            const int h = c >> 4, d = c & 15;
            if (sel == 2) {
                const size_t base = ((size_t)((b * HH + h) * DD + d)) * TT + t;
                __nv_bfloat16 h0 = __float2bfloat16_rn(acc[nt][0]);
                __nv_bfloat16 h1 = __float2bfloat16_rn(acc[nt][1]);
                __nv_bfloat16 h2 = __float2bfloat16_rn(acc[nt][2]);
                __nv_bfloat16 h3 = __float2bfloat16_rn(acc[nt][3]);
                g_vth[base]          = h0;
                g_vth[base + TT]     = h1;
                g_vth[base + 8]      = h2;
                g_vth[base + TT + 8] = h3;
                g_vtl[base]          = __float2bfloat16_rn(acc[nt][0] - __bfloat162float(h0));
                g_vtl[base + TT]     = __float2bfloat16_rn(acc[nt][1] - __bfloat162float(h1));
                g_vtl[base + 8]      = __float2bfloat16_rn(acc[nt][2] - __bfloat162float(h2));
                g_vtl[base + TT + 8] = __float2bfloat16_rn(acc[nt][3] - __bfloat162float(h3));
            } else {
                const size_t base = ((size_t)(b * HH + h) * TT + t) * DD + d;
                const float s = (sel == 0) ? QSCALE : 1.0f;
                __nv_bfloat16* dst = ((sel == 0) ? g_qb : g_kb) + base;
                *(uint32_t*)(dst)          = pack2(acc[nt][0] * s, acc[nt][1] * s);
                *(uint32_t*)(dst + 8 * DD) = pack2(acc[nt][2] * s, acc[nt][3] * s);
            }
        }
    }
}

// ---------------------------------------------------------------------------
// Split-K flash attention. Block = (bh, qi, split); split covers <=4 key tiles.
// exp via MUFU ex2. K/V fragments loaded via ldmatrix.x4 (bit-identical to
// the previous scalar LDS path; 24 LDS -> 6 LDSM per chunk).
// Row sums from ph-only ones column. Partial O and l via red.global.add.
// ---------------------------------------------------------------------------
#define KPITCH 48
#define VPLANE 4352              // 16 * 272
#define VBUF   (2*VPLANE)        // 8704

__global__ __launch_bounds__(128, 4) void attn_kernel()
{
    __shared__ __align__(16) char ksm[2][128 * KPITCH];  // 12 KB
    __shared__ __align__(16) char vsm[2][VBUF];          // 17 KB

    const int tid  = threadIdx.x;
    const int wid  = tid >> 5;
    const int lane = tid & 31;
    const int g    = lane >> 2;
    const int q4   = lane & 3;
    const int bh   = blockIdx.y;

    // ---- map blockIdx.x (0..143) -> (qi, split) ----
    const int x = blockIdx.x;
    int a = (int)((sqrtf((float)(2 * x) + 1.0f) - 1.0f) * 0.5f);
    while (2 * (a + 1) * (a + 2) <= x) ++a;
    while (2 * a * (a + 1) > x) --a;
    const int r  = x - 2 * a * (a + 1);
    const int qi    = 4 * a + r / (a + 1);
    const int split = r % (a + 1);
    const int kt0   = 4 * split;
    const int ktend = (split == a) ? (qi + 1) : (kt0 + 4);

    // ---- ldmatrix lane-address invariants ----
    const int lrow = lane & 7;          // row within 8x8 tile
    const int lt   = lane >> 3;         // tile index 0..3
    const int ltn  = lt >> 1;           // n-subtile
    const int lth  = lt & 1;            // k-half
    // K: tile (ntb+ltn, kh=lth), row key = kc + (ntb+ltn)*8 + lrow
    const uint32_t koff_inv0 = (uint32_t)(((0 + ltn) * 8 + lrow) * KPITCH + lth * 16);
    const uint32_t koff_inv2 = (uint32_t)(((2 + ltn) * 8 + lrow) * KPITCH + lth * 16);
    // V: tile (nt=ltn, kh=lth), row d = ltn*8 + lrow, key byte = (kc+16s)*2 + lth*16
    const uint32_t voff_inv = (uint32_t)((ltn * 8 + lrow) * 272 + lth * 16);

    // ---- Q fragments (bf16, pre-scaled by 0.25*log2e) ----
    const __nv_bfloat16* Qb = g_qb + ((size_t)bh * TT + (size_t)qi * 128 + wid * 32) * DD;
    uint32_t qa[2][4];
    #pragma unroll
    for (int m = 0; m < 2; ++m) {
        const int r0 = 16 * m + g;
        qa[m][0] = *(const uint32_t*)(Qb + (size_t)r0 * DD + 2 * q4);
        qa[m][1] = *(const uint32_t*)(Qb + (size_t)(r0 + 8) * DD + 2 * q4);
        qa[m][2] = *(const uint32_t*)(Qb + (size_t)r0 * DD + 2 * q4 + 8);
        qa[m][3] = *(const uint32_t*)(Qb + (size_t)(r0 + 8) * DD + 2 * q4 + 8);
    }

    // O accumulators: [m][n 0..1 = V cols, 2 = ones column (row sums)]
    float O[2][3][4];
    #pragma unroll
    for (int m = 0; m < 2; ++m)
        #pragma unroll
        for (int n = 0; n < 3; ++n)
            #pragma unroll
            for (int rr = 0; rr < 4; ++rr) O[m][n][rr] = 0.f;

    const uint32_t vone = (g == 0) ? 0x3F803F80u : 0u;
    const uint32_t vones[2] = {vone, vone};

    const char* Kg  = (const char*)(g_kb  + ((size_t)bh * TT) * DD);
    const char* Vhg = (const char*)(g_vth + (size_t)bh * DD * TT);
    const char* Vlg = (const char*)(g_vtl + (size_t)bh * DD * TT);

    const int cid0 = tid * 4;

    // ---- stage first tile ----
    {
        uint32_t kd = sm_u32(&ksm[0][tid * KPITCH]);
        const char* ks = Kg + ((size_t)kt0 * 128 + tid) * 32;
        CP_ASYNC16(kd, ks); CP_ASYNC16(kd + 16, ks + 16);
        #pragma unroll
        for (int i = 0; i < 4; ++i) {
            const int cid = cid0 + i;
            const int pl = cid >> 8, d = (cid >> 4) & 15, ch = cid & 15;
            const char* src = (pl ? Vlg : Vhg) + ((size_t)d * TT + (size_t)kt0 * 128) * 2 + ch * 16;
            CP_ASYNC16(sm_u32(&vsm[0][pl * VPLANE + d * 272 + ch * 16]), src);
        }
        CP_COMMIT();
    }

    for (int kt = kt0; kt < ktend; ++kt) {
        const int buf = (kt - kt0) & 1;
        if (kt + 1 < ktend) {
            const int nb = buf ^ 1;
            uint32_t kd = sm_u32(&ksm[nb][tid * KPITCH]);
            const char* ks = Kg + ((size_t)(kt + 1) * 128 + tid) * 32;
            CP_ASYNC16(kd, ks); CP_ASYNC16(kd + 16, ks + 16);
            #pragma unroll
            for (int i = 0; i < 4; ++i) {
                const int cid = cid0 + i;
                const int pl = cid >> 8, d = (cid >> 4) & 15, ch = cid & 15;
                const char* src = (pl ? Vlg : Vhg) + ((size_t)d * TT + (size_t)(kt + 1) * 128) * 2 + ch * 16;
                CP_ASYNC16(sm_u32(&vsm[nb][pl * VPLANE + d * 272 + ch * 16]), src);
            }
            CP_COMMIT();
            CP_WAIT1();
        } else {
            CP_WAIT0();
        }
        __syncthreads();

        const uint32_t kbuf_u32 = sm_u32(ksm[buf]);
        const uint32_t vhi_u32  = sm_u32(vsm[buf]);
        const uint32_t vlo_u32  = vhi_u32 + VPLANE;
        const bool diag = (kt == qi);
        const int nchunk = diag ? (wid + 1) : 4;

        for (int c = 0; c < nchunk; ++c) {
            const int kc = 32 * c;

            // K B-fragments via ldmatrix (2x x4)
            uint32_t kb[4][2];
            {
                const uint32_t base = kbuf_u32 + (uint32_t)(kc * KPITCH);
                LDSM_X4(kb[0][0], kb[0][1], kb[1][0], kb[1][1], base + koff_inv0);
                LDSM_X4(kb[2][0], kb[2][1], kb[3][0], kb[3][1], base + koff_inv2);
            }

            // V B-fragments via ldmatrix (4x x4)
            uint32_t vh[2][2][2], vl[2][2][2];
            {
                const uint32_t kb0 = (uint32_t)(kc * 2);
                LDSM_X4(vh[0][0][0], vh[0][0][1], vh[0][1][0], vh[0][1][1], vhi_u32 + voff_inv + kb0);
                LDSM_X4(vh[1][0][0], vh[1][0][1], vh[1][1][0], vh[1][1][1], vhi_u32 + voff_inv + kb0 + 32);
                LDSM_X4(vl[0][0][0], vl[0][0][1], vl[0][1][0], vl[0][1][1], vlo_u32 + voff_inv + kb0);
                LDSM_X4(vl[1][0][0], vl[1][0][1], vl[1][1][0], vl[1][1][1], vlo_u32 + voff_inv + kb0 + 32);
            }

            // QK (single bf16 pass; scores in log2 domain)
            float S[2][4][4];
            #pragma unroll
            for (int m = 0; m < 2; ++m)
                #pragma unroll
                for (int nt = 0; nt < 4; ++nt)
                    mma16816_init(S[m][nt], qa[m], kb[nt]);

            // softmax weights: p = 2^s via MUFU (idle pipe)
            const bool dmask = diag && (c == wid);
            #pragma unroll
            for (int m = 0; m < 2; ++m) {
                const int ql0 = 32 * wid + 16 * m + g;
                #pragma unroll
                for (int nt = 0; nt < 4; ++nt) {
                    const int kl = kc + nt * 8 + 2 * q4;
                    float p0 = ex2f(S[m][nt][0]);
                    float p1 = ex2f(S[m][nt][1]);
                    float p2 = ex2f(S[m][nt][2]);
                    float p3 = ex2f(S[m][nt][3]);
                    if (dmask) {
                        if (kl     > ql0)     p0 = 0.f;
                        if (kl + 1 > ql0)     p1 = 0.f;
                        if (kl     > ql0 + 8) p2 = 0.f;
                        if (kl + 1 > ql0 + 8) p3 = 0.f;
                    }
                    S[m][nt][0] = p0; S[m][nt][1] = p1;
                    S[m][nt][2] = p2; S[m][nt][3] = p3;
                }
            }

            // pack P hi/lo A-fragments
            uint32_t ph[2][2][4], pl[2][2][4];
            #pragma unroll
            for (int m = 0; m < 2; ++m)
                #pragma unroll
                for (int s = 0; s < 2; ++s) {
                    const float* t0 = S[m][2 * s];
                    const float* t1 = S[m][2 * s + 1];
                    ph[m][s][0] = pack2(t0[0], t0[1]);
                    ph[m][s][1] = pack2(t0[2], t0[3]);
                    ph[m][s][2] = pack2(t1[0], t1[1]);
                    ph[m][s][3] = pack2(t1[2], t1[3]);
                    pl[m][s][0] = pack2(t0[0] - bflo(ph[m][s][0]), t0[1] - bfhi(ph[m][s][0]));
                    pl[m][s][1] = pack2(t0[2] - bflo(ph[m][s][1]), t0[3] - bfhi(ph[m][s][1]));
                    pl[m][s][2] = pack2(t1[0] - bflo(ph[m][s][2]), t1[1] - bfhi(ph[m][s][2]));
                    pl[m][s][3] = pack2(t1[2] - bflo(ph[m][s][3]), t1[3] - bfhi(ph[m][s][3]));
                }

            // PV (+ones for row sums; ph-only l)
            #pragma unroll
            for (int m = 0; m < 2; ++m)
                #pragma unroll
                for (int s = 0; s < 2; ++s) {
                    mma16816(O[m][0], ph[m][s], vh[s][0]);
                    mma16816(O[m][1], ph[m][s], vh[s][1]);
                    mma16816(O[m][2], ph[m][s], vones);
                    mma16816(O[m][0], pl[m][s], vh[s][0]);
                    mma16816(O[m][1], pl[m][s], vh[s][1]);
                    mma16816(O[m][0], ph[m][s], vl[s][0]);
                    mma16816(O[m][1], ph[m][s], vl[s][1]);
                }
        }
        __syncthreads();
    }

    // ---- epilogue: atomic accumulate partial O and l ----
    const int b = bh >> 3, h = bh & 7;
    #pragma unroll
    for (int m = 0; m < 2; ++m) {
        const int row0 = qi * 128 + 32 * wid + 16 * m + g;
        if (q4 == 0) {
            REDADD(&g_l[(size_t)(b * TT + row0) * HH + h],     O[m][2][0]);
            REDADD(&g_l[(size_t)(b * TT + row0 + 8) * HH + h], O[m][2][2]);
        }
        #pragma unroll
        for (int nt = 0; nt < 2; ++nt) {
            const int d = nt * 8 + 2 * q4;
            float* p0 = g_att + (size_t)(b * TT + row0) * CC + h * DD + d;
            float* p1 = g_att + (size_t)(b * TT + row0 + 8) * CC + h * DD + d;
            REDADD(p0,     O[m][nt][0]);
            REDADD(p0 + 1, O[m][nt][1]);
            REDADD(p1,     O[m][nt][2]);
            REDADD(p1 + 1, O[m][nt][3]);
        }
    }
}

// ---------------------------------------------------------------------------
// Launch: prep(+zero) -> fused QKV tgemm -> attention -> proj tgemm (fused norm)
// inputs (metadata order): x, Wk, Wq, Wv, Wp, bp
// ---------------------------------------------------------------------------
extern "C" void kernel_launch(void* const* d_in, const int* in_sizes, int n_in,
                              void* d_out, int out_size)
{
    const float* x  = (const float*)d_in[0];
    const float* Wk = (const float*)d_in[1];
    const float* Wq = (const float*)d_in[2];
    const float* Wv = (const float*)d_in[3];
    const float* Wp = (const float*)d_in[4];
    const float* bp = (const float*)d_in[5];
    float* out = (float*)d_out;

    cudaFuncSetAttribute(tgemm_kernel, cudaFuncAttributeMaxDynamicSharedMemorySize, TG_SMEM);

    prep_kernel<<<PREP_TOT4 / 256, 256>>>(x, Wk, Wq, Wv, Wp);

    dim3 qkv_grid(MROWS / TG_ROWS, 3);   // (128, 3)
    tgemm_kernel<<<qkv_grid, 256, TG_SMEM>>>(nullptr, nullptr, -1);  // Q,K,V fused

    dim3 agrid(144, NBH);
    attn_kernel<<<agrid, 128>>>();

    tgemm_kernel<<<MROWS / TG_ROWS, 256, TG_SMEM>>>(bp, out, 3);  // proj + fused norm
}